// round 9
// baseline (speedup 1.0000x reference)
#include <cuda_runtime.h>
#include <math.h>

#define BATCH 4
#define CC 64
#define HH 192
#define WW 192
#define NN (HH*WW)
#define NELEM (BATCH*CC*NN)
#define TP 128

__device__ float g_scratch[(size_t)11 * NELEM];
__device__ float g_gram[512*1024];
__device__ float g_normp[512*64];
__device__ float g_attnw[8*1024];

typedef unsigned long long u64;

__device__ __forceinline__ u64 pack2(float a, float b){
  u64 r;
  asm("mov.b64 %0, {%1,%2};" : "=l"(r) : "r"(__float_as_uint(a)), "r"(__float_as_uint(b)));
  return r;
}
__device__ __forceinline__ void unpack2(u64 v, float &a, float &b){
  unsigned lo, hi;
  asm("mov.b64 {%0,%1}, %2;" : "=r"(lo), "=r"(hi) : "l"(v));
  a = __uint_as_float(lo); b = __uint_as_float(hi);
}
__device__ __forceinline__ void ffma2(u64 &d, u64 a, u64 b){
  asm("fma.rn.f32x2 %0, %1, %2, %0;" : "+l"(d) : "l"(a), "l"(b));
}
__device__ __forceinline__ float gelu_f(float x){
  return 0.5f*x*(1.0f + erff(x*0.70710678118654752f));
}

// fill duplicated X tile: per channel row (256 floats):
//   group0 [0,128): lane l -> (x[4l],x[4l],x[4l+1],x[4l+1])
//   group1 [128,256): lane l -> (x[4l+2],x[4l+2],x[4l+3],x[4l+3])
__device__ __forceinline__ void fill_dup(float* xs, const float* xb, int tid){
  for (int i = tid; i < 2048; i += 256){
    int c = i >> 5, q = i & 31;
    float4 v = *(const float4*)(xb + (size_t)c*NN + q*4);
    *(float4*)(xs + c*256 + q*4)       = make_float4(v.x, v.x, v.y, v.y);
    *(float4*)(xs + c*256 + 128 + q*4) = make_float4(v.z, v.z, v.w, v.w);
  }
}

// one k-step: 16 FFMA2 against 8 outputs x 4 pixels
#define CONV_STEP(ACC, XROW, WROW, K)                                           \
  {                                                                             \
    ulonglong2 xv01 = *(const ulonglong2*)((XROW) + (K)*256);                   \
    ulonglong2 xv23 = *(const ulonglong2*)((XROW) + (K)*256 + 128);             \
    ulonglong2 wv0  = *(const ulonglong2*)((WROW) + (K)*68);                    \
    ulonglong2 wv1  = *(const ulonglong2*)((WROW) + (K)*68 + 4);                \
    ffma2(ACC[0],  wv0.x, xv01.x); ffma2(ACC[1],  wv0.x, xv01.y);               \
    ffma2(ACC[2],  wv0.x, xv23.x); ffma2(ACC[3],  wv0.x, xv23.y);               \
    ffma2(ACC[4],  wv0.y, xv01.x); ffma2(ACC[5],  wv0.y, xv01.y);               \
    ffma2(ACC[6],  wv0.y, xv23.x); ffma2(ACC[7],  wv0.y, xv23.y);               \
    ffma2(ACC[8],  wv1.x, xv01.x); ffma2(ACC[9],  wv1.x, xv01.y);               \
    ffma2(ACC[10], wv1.x, xv23.x); ffma2(ACC[11], wv1.x, xv23.y);               \
    ffma2(ACC[12], wv1.y, xv01.x); ffma2(ACC[13], wv1.y, xv01.y);               \
    ffma2(ACC[14], wv1.y, xv23.x); ffma2(ACC[15], wv1.y, xv23.y);               \
  }

// epilogue: acc[pp*4+px] = (y[o=base+2pp], y[o=base+2pp+1]) at pixel px
__device__ __forceinline__ void store8(
    u64* acc, float* yb, int obase, int lane,
    const float* bias, const float* bias2, int do_gelu)
{
  #pragma unroll
  for (int pp = 0; pp < 4; pp++){
    float lo0,hi0,lo1,hi1,lo2,hi2,lo3,hi3;
    unpack2(acc[pp*4+0], lo0, hi0);
    unpack2(acc[pp*4+1], lo1, hi1);
    unpack2(acc[pp*4+2], lo2, hi2);
    unpack2(acc[pp*4+3], lo3, hi3);
    int o = obase + 2*pp;
    float b0 = bias ? bias[o] : 0.f;
    float b1 = bias ? bias[o+1] : 0.f;
    if (bias2){ b0 += bias2[o]; b1 += bias2[o+1]; }
    lo0+=b0; lo1+=b0; lo2+=b0; lo3+=b0;
    hi0+=b1; hi1+=b1; hi2+=b1; hi3+=b1;
    if (do_gelu){
      lo0=gelu_f(lo0); lo1=gelu_f(lo1); lo2=gelu_f(lo2); lo3=gelu_f(lo3);
      hi0=gelu_f(hi0); hi1=gelu_f(hi1); hi2=gelu_f(hi2); hi3=gelu_f(hi3);
    }
    *(float4*)(yb + (size_t)o*NN     + lane*4) = make_float4(lo0,lo1,lo2,lo3);
    *(float4*)(yb + (size_t)(o+1)*NN + lane*4) = make_float4(hi0,hi1,hi2,hi3);
  }
}

// NOTE: acc[pp*4+px] ordering vs store8: acc index = output-pair pp, pixel px:
// CONV_STEP fills ACC[pair*4 + pixel], matching store8. (pair = wv half)

// ================= single-matrix conv1x1 (64->64) =================
__global__ void __launch_bounds__(256,2) k_conv1(
    const float* __restrict__ ext_in, int in_slice,
    float* __restrict__ ext_out, int out_slice,
    const float* __restrict__ w, int ldw,
    const float* __restrict__ bias, int do_gelu)
{
  extern __shared__ float sm[];
  float* xs = sm;              // [64][256] duplicated
  float* ws = sm + 64*256;     // [64][68]  ws[c*68+o] = w[o][c]
  int tid = threadIdx.x, lane = tid & 31, wid = tid >> 5;
  const float* xin = (in_slice >= 0) ? g_scratch + (size_t)in_slice*NELEM : ext_in;
  float* yout = (out_slice >= 0) ? g_scratch + (size_t)out_slice*NELEM : ext_out;
  for (int i = tid; i < 4096; i += 256){
    int c = i & 63, o = i >> 6;
    ws[c*68 + o] = w[o*ldw + c];
  }
  int p0 = blockIdx.x * TP;
  int b = p0 / NN, n0 = p0 - b*NN;
  const float* xb = xin + (size_t)b*(CC*NN) + n0;
  fill_dup(xs, xb, tid);
  __syncthreads();
  u64 acc[16];
  u64 z = pack2(0.f, 0.f);
  #pragma unroll
  for (int i = 0; i < 16; i++) acc[i] = z;
  const float* xrow = xs + lane*4;
  const float* wrow = ws + wid*8;
  #pragma unroll 8
  for (int k = 0; k < 64; k++) CONV_STEP(acc, xrow, wrow, k);
  float* yb = yout + (size_t)b*(CC*NN) + n0;
  store8(acc, yb, wid*8, lane, bias, nullptr, do_gelu);
}

// ================= dual-output conv1x1 =================
__global__ void __launch_bounds__(256,2) k_conv2(
    int in_slice, int outA, int outB,
    const float* __restrict__ wA, const float* __restrict__ wB)
{
  extern __shared__ float sm[];
  float* xs  = sm;               // [64][256]
  float* wsA = sm + 64*256;      // [64][68]
  float* wsB = wsA + 64*68;
  int tid = threadIdx.x, lane = tid & 31, wid = tid >> 5;
  for (int i = tid; i < 4096; i += 256){
    int c = i & 63, o = i >> 6;
    wsA[c*68 + o] = wA[o*64 + c];
    wsB[c*68 + o] = wB[o*64 + c];
  }
  int p0 = blockIdx.x * TP;
  int b = p0 / NN, n0 = p0 - b*NN;
  const float* xb = g_scratch + (size_t)in_slice*NELEM + (size_t)b*(CC*NN) + n0;
  fill_dup(xs, xb, tid);
  __syncthreads();
  u64 accA[16], accB[16];
  u64 z = pack2(0.f, 0.f);
  #pragma unroll
  for (int i = 0; i < 16; i++){ accA[i] = z; accB[i] = z; }
  const float* xrow = xs + lane*4;
  const float* wra = wsA + wid*8;
  const float* wrb = wsB + wid*8;
  #pragma unroll 4
  for (int k = 0; k < 64; k++){
    CONV_STEP(accA, xrow, wra, k);
    CONV_STEP(accB, xrow, wrb, k);
  }
  size_t boff = (size_t)b*(CC*NN) + n0;
  store8(accA, g_scratch + (size_t)outA*NELEM + boff, wid*8, lane, nullptr, nullptr, 0);
  store8(accB, g_scratch + (size_t)outB*NELEM + boff, wid*8, lane, nullptr, nullptr, 0);
}

// ================= dual-input conv1x1 (two phases, shared dup buffer) =================
__global__ void __launch_bounds__(256,2) k_convDI(
    int inA_slice, const float* __restrict__ extB, int out_slice,
    const float* __restrict__ wA, const float* __restrict__ bA,
    const float* __restrict__ wB, const float* __restrict__ bB)
{
  extern __shared__ float sm[];
  float* xs  = sm;               // [64][256]
  float* wsA = sm + 64*256;      // [64][68]
  float* wsB = wsA + 64*68;
  int tid = threadIdx.x, lane = tid & 31, wid = tid >> 5;
  for (int i = tid; i < 4096; i += 256){
    int c = i & 63, o = i >> 6;
    wsA[c*68 + o] = wA[o*64 + c];
    wsB[c*68 + o] = wB[o*64 + c];
  }
  int p0 = blockIdx.x * TP;
  int b = p0 / NN, n0 = p0 - b*NN;
  size_t boff = (size_t)b*(CC*NN) + n0;
  u64 acc[16];
  u64 z = pack2(0.f, 0.f);
  #pragma unroll
  for (int i = 0; i < 16; i++) acc[i] = z;
  const float* xrow = xs + lane*4;
  // phase A
  fill_dup(xs, g_scratch + (size_t)inA_slice*NELEM + boff, tid);
  __syncthreads();
  {
    const float* wrow = wsA + wid*8;
    #pragma unroll 8
    for (int k = 0; k < 64; k++) CONV_STEP(acc, xrow, wrow, k);
  }
  __syncthreads();
  // phase B
  fill_dup(xs, extB + boff, tid);
  __syncthreads();
  {
    const float* wrow = wsB + wid*8;
    #pragma unroll 8
    for (int k = 0; k < 64; k++) CONV_STEP(acc, xrow, wrow, k);
  }
  store8(acc, g_scratch + (size_t)out_slice*NELEM + boff, wid*8, lane, bA, bB, 0);
}

// ================= final conv 192->64 (3 phases) + GELU =================
__global__ void __launch_bounds__(256,2) k_final3(
    int s1, int s2, int s3,
    const float* __restrict__ w, const float* __restrict__ bias,
    float* __restrict__ out)
{
  extern __shared__ float sm[];
  float* xs = sm;              // [64][256]
  float* ws = sm + 64*256;     // [64][68] per phase
  int tid = threadIdx.x, lane = tid & 31, wid = tid >> 5;
  int p0 = blockIdx.x * TP;
  int b = p0 / NN, n0 = p0 - b*NN;
  size_t boff = (size_t)b*(CC*NN) + n0;
  u64 acc[16];
  u64 z = pack2(0.f, 0.f);
  #pragma unroll
  for (int i = 0; i < 16; i++) acc[i] = z;
  const float* xrow = xs + lane*4;
  const float* wrow = ws + wid*8;
  int slices[3] = {s1, s2, s3};
  for (int p = 0; p < 3; p++){
    __syncthreads();
    for (int i = tid; i < 4096; i += 256){
      int c = i & 63, o = i >> 6;
      ws[c*68 + o] = w[o*192 + p*64 + c];
    }
    fill_dup(xs, g_scratch + (size_t)slices[p]*NELEM + boff, tid);
    __syncthreads();
    #pragma unroll 8
    for (int k = 0; k < 64; k++) CONV_STEP(acc, xrow, wrow, k);
  }
  store8(acc, out + boff, wid*8, lane, bias, nullptr, 1);
}

// ================= channel-attention apply (block-diag 2x 32x32) =================
__global__ void __launch_bounds__(256,3) k_apply_t(int v_slice, int out_slice)
{
  extern __shared__ float sm[];
  float* xs = sm;             // [64][256]
  float* ws = sm + 64*256;    // [2*32][36] : ws[(g*32+k)*36 + o] = attn[b,g,o,k]
  int tid = threadIdx.x, lane = tid & 31, wid = tid >> 5;
  int p0 = blockIdx.x * TP;
  int b = p0 / NN, n0 = p0 - b*NN;
  for (int i = tid; i < 2048; i += 256){
    int g = i >> 10, rem = i & 1023;
    int o = rem >> 5, k = rem & 31;
    ws[(g*32 + k)*36 + o] = g_attnw[(size_t)(b*2+g)*1024 + o*32 + k];
  }
  const float* xb = g_scratch + (size_t)v_slice*NELEM + (size_t)b*(CC*NN) + n0;
  fill_dup(xs, xb, tid);
  __syncthreads();
  int g = wid >> 2;
  int ow = (wid & 3) * 8;
  u64 acc[16];
  u64 z = pack2(0.f, 0.f);
  #pragma unroll
  for (int i = 0; i < 16; i++) acc[i] = z;
  const float* xrow = xs + g*32*256 + lane*4;
  const float* wrow0 = ws + g*32*36 + ow;
  #pragma unroll 8
  for (int k = 0; k < 32; k++){
    ulonglong2 xv01 = *(const ulonglong2*)(xrow + k*256);
    ulonglong2 xv23 = *(const ulonglong2*)(xrow + k*256 + 128);
    ulonglong2 wv0  = *(const ulonglong2*)(wrow0 + k*36);
    ulonglong2 wv1  = *(const ulonglong2*)(wrow0 + k*36 + 4);
    ffma2(acc[0],  wv0.x, xv01.x); ffma2(acc[1],  wv0.x, xv01.y);
    ffma2(acc[2],  wv0.x, xv23.x); ffma2(acc[3],  wv0.x, xv23.y);
    ffma2(acc[4],  wv0.y, xv01.x); ffma2(acc[5],  wv0.y, xv01.y);
    ffma2(acc[6],  wv0.y, xv23.x); ffma2(acc[7],  wv0.y, xv23.y);
    ffma2(acc[8],  wv1.x, xv01.x); ffma2(acc[9],  wv1.x, xv01.y);
    ffma2(acc[10], wv1.x, xv23.x); ffma2(acc[11], wv1.x, xv23.y);
    ffma2(acc[12], wv1.y, xv01.x); ffma2(acc[13], wv1.y, xv01.y);
    ffma2(acc[14], wv1.y, xv23.x); ffma2(acc[15], wv1.y, xv23.y);
  }
  float* yb = g_scratch + (size_t)out_slice*NELEM + (size_t)b*(CC*NN) + n0;
  store8(acc, yb, g*32 + ow, lane, nullptr, nullptr, 0);
}

// ================= depthwise 3x3 + bias + exact GELU =================
__global__ void __launch_bounds__(256) k_dwgelu(
    int in_slice, int out_slice,
    const float* __restrict__ dw_w, const float* __restrict__ dw_b)
{
  int e = blockIdx.x*256 + threadIdx.x;
  const float* tin = g_scratch + (size_t)in_slice*NELEM;
  int n  = e % NN;
  int bc = e / NN;
  int c  = bc & 63;
  int h = n / WW, w = n - h*WW;
  const float* plane = tin + (size_t)bc*NN;
  float s = dw_b[c];
  #pragma unroll
  for (int ky = 0; ky < 3; ky++){
    int hh = h + ky - 1;
    if ((unsigned)hh >= (unsigned)HH) continue;
    #pragma unroll
    for (int kx = 0; kx < 3; kx++){
      int wx = w + kx - 1;
      if ((unsigned)wx >= (unsigned)WW) continue;
      s += dw_w[c*9 + ky*3 + kx] * plane[hh*WW + wx];
    }
  }
  g_scratch[(size_t)out_slice*NELEM + e] = gelu_f(s);
}

// ================= split-K gram + norms =================
__global__ void __launch_bounds__(256) k_gram(int q_slice, int k_slice)
{
  int blk = blockIdx.x;
  int s  = blk & 63;
  int bg = blk >> 6;
  int g = bg & 1, b = bg >> 1;
  int n0 = s * 576;
  const float* qb = g_scratch + (size_t)q_slice*NELEM + (size_t)(b*64 + g*32)*NN;
  const float* kb = g_scratch + (size_t)k_slice*NELEM + (size_t)(b*64 + g*32)*NN;
  __shared__ float qs[32][65];
  __shared__ float ks[32][65];
  int t = threadIdx.x;
  int i = t & 31, jb = t >> 5;
  float acc[4] = {0.f,0.f,0.f,0.f};
  float nacc = 0.f;
  for (int ch = 0; ch < 9; ch++){
    int nb = n0 + ch*64;
    __syncthreads();
    for (int idx = t; idx < 2048; idx += 256){
      int r = idx >> 6, nn = idx & 63;
      qs[r][nn] = qb[(size_t)r*NN + nb + nn];
      ks[r][nn] = kb[(size_t)r*NN + nb + nn];
    }
    __syncthreads();
    #pragma unroll 8
    for (int nn = 0; nn < 64; nn++){
      float qv = qs[i][nn];
      acc[0] += qv * ks[jb*4+0][nn];
      acc[1] += qv * ks[jb*4+1][nn];
      acc[2] += qv * ks[jb*4+2][nn];
      acc[3] += qv * ks[jb*4+3][nn];
    }
    if (t < 32){
      #pragma unroll 8
      for (int nn = 0; nn < 64; nn++){ float v = qs[t][nn]; nacc += v*v; }
    } else if (t < 64){
      int r = t - 32;
      #pragma unroll 8
      for (int nn = 0; nn < 64; nn++){ float v = ks[r][nn]; nacc += v*v; }
    }
  }
  float* Gp = g_gram + (size_t)blk*1024;
  #pragma unroll
  for (int jj = 0; jj < 4; jj++) Gp[i*32 + jb*4 + jj] = acc[jj];
  if (t < 64) g_normp[(size_t)blk*64 + t] = nacc;
}

// ================= gram finalize + softmax =================
__global__ void __launch_bounds__(1024) k_attnsoft(const float* __restrict__ temperature)
{
  int bg = blockIdx.x;
  int g = bg & 1;
  int t = threadIdx.x;
  int i = t >> 5, j = t & 31;
  __shared__ float nq[32], nk[32];
  if (t < 64){
    float s = 0.f;
    for (int ss = 0; ss < 64; ss++) s += g_normp[(size_t)(bg*64 + ss)*64 + t];
    float nv = fmaxf(sqrtf(s), 1e-12f);
    if (t < 32) nq[t] = nv; else nk[t-32] = nv;
  }
  float G = 0.f;
  for (int ss = 0; ss < 64; ss++) G += g_gram[(size_t)(bg*64 + ss)*1024 + t];
  __syncthreads();
  float logit = G / (nq[i]*nk[j]) * temperature[g];
  float m = logit;
  #pragma unroll
  for (int o = 16; o > 0; o >>= 1) m = fmaxf(m, __shfl_xor_sync(0xffffffffu, m, o));
  float e = __expf(logit - m);
  float ssum = e;
  #pragma unroll
  for (int o = 16; o > 0; o >>= 1) ssum += __shfl_xor_sync(0xffffffffu, ssum, o);
  g_attnw[(size_t)bg*1024 + t] = e / ssum;
}

// ================= line attention, single-pass (logits bounded -> no max) =================
__global__ void __launch_bounds__(192, 2) k_lineattn(
    int q_slice, int k_slice, int v_slice, int x_slice, int out_slice,
    const float* __restrict__ gamma_p)
{
  extern __shared__ float smem[];
  float* Ksh = smem;                 // [192][68], j-major
  float* Vsh = smem + 192*68;
  int blk = blockIdx.x;
  int h = blk % HH;
  int b = blk / HH;
  size_t base = (size_t)b*(CC*NN) + (size_t)h*WW;
  const float* Qb = g_scratch + (size_t)q_slice*NELEM + base;
  const float* Kb = g_scratch + (size_t)k_slice*NELEM + base;
  const float* Vb = g_scratch + (size_t)v_slice*NELEM + base;
  const float* Xb = g_scratch + (size_t)x_slice*NELEM + base;
  float* Ob = g_scratch + (size_t)out_slice*NELEM + base;
  int t = threadIdx.x;
  for (int idx = t; idx < 64*192; idx += 192){
    int c = idx / 192;
    int j = idx - c*192;
    Ksh[j*68 + c] = Kb[(size_t)c*NN + j];
    Vsh[j*68 + c] = Vb[(size_t)c*NN + j];
  }
  u64 q2[32];
  #pragma unroll
  for (int cc = 0; cc < 32; cc++)
    q2[cc] = pack2(Qb[(size_t)(2*cc)*NN + t], Qb[(size_t)(2*cc+1)*NN + t]);
  __syncthreads();
  u64 z = pack2(0.f, 0.f);
  u64 acc[32];
  #pragma unroll
  for (int cc = 0; cc < 32; cc++) acc[cc] = z;
  float l = 0.f;
  #pragma unroll 2
  for (int j = 0; j < 192; j++){
    const ulonglong2* kr = (const ulonglong2*)(Ksh + j*68);
    u64 a0 = z, a1 = z, a2 = z, a3 = z;
    #pragma unroll
    for (int cc = 0; cc < 16; cc += 2){
      ulonglong2 kv0 = kr[cc];
      ulonglong2 kv1 = kr[cc+1];
      ffma2(a0, q2[2*cc+0], kv0.x);
      ffma2(a1, q2[2*cc+1], kv0.y);
      ffma2(a2, q2[2*cc+2], kv1.x);
      ffma2(a3, q2[2*cc+3], kv1.y);
    }
    float x0,y0,x1,y1,x2,y2,x3,y3;
    unpack2(a0,x0,y0); unpack2(a1,x1,y1); unpack2(a2,x2,y2); unpack2(a3,x3,y3);
    float s = ((x0+y0)+(x1+y1)) + ((x2+y2)+(x3+y3));
    float p = __expf(s);
    l += p;
    u64 ps = pack2(p, p);
    const ulonglong2* vr = (const ulonglong2*)(Vsh + j*68);
    #pragma unroll
    for (int cc = 0; cc < 16; cc++){
      ulonglong2 vv = vr[cc];
      ffma2(acc[2*cc],   ps, vv.x);
      ffma2(acc[2*cc+1], ps, vv.y);
    }
  }
  float gam = gamma_p[0] / l;
  #pragma unroll
  for (int cc = 0; cc < 32; cc++){
    float a0, a1; unpack2(acc[cc], a0, a1);
    Ob[(size_t)(2*cc)*NN + t]   = gam*a0 + Xb[(size_t)(2*cc)*NN + t];
    Ob[(size_t)(2*cc+1)*NN + t] = gam*a1 + Xb[(size_t)(2*cc+1)*NN + t];
  }
}

// ================= per-plane 192x192 transpose =================
__global__ void k_transpose(int in_slice, int out_slice)
{
  __shared__ float tile[32][33];
  const float* in = g_scratch + (size_t)in_slice*NELEM + (size_t)blockIdx.z*NN;
  float* out      = g_scratch + (size_t)out_slice*NELEM + (size_t)blockIdx.z*NN;
  int x0 = blockIdx.x*32, y0 = blockIdx.y*32;
  int tx = threadIdx.x, ty = threadIdx.y;
  #pragma unroll
  for (int k = 0; k < 32; k += 8)
    tile[ty+k][tx] = in[(size_t)(y0+ty+k)*WW + x0+tx];
  __syncthreads();
  #pragma unroll
  for (int k = 0; k < 32; k += 8)
    out[(size_t)(x0+ty+k)*HH + y0+tx] = tile[tx][ty+k];
}

extern "C" void kernel_launch(void* const* d_in, const int* in_sizes, int n_in,
                              void* d_out, int out_size)
{
  const float* x    = (const float*)d_in[0];
  const float* pw_w = (const float*)d_in[1];
  const float* dw_w = (const float*)d_in[2];
  const float* dw_b = (const float*)d_in[3];
  const float* c2w  = (const float*)d_in[4];
  const float* c2b  = (const float*)d_in[5];
  const float* c0w  = (const float*)d_in[6];
  const float* c0b  = (const float*)d_in[7];
  const float* aq   = (const float*)d_in[8];
  const float* ak   = (const float*)d_in[9];
  const float* av   = (const float*)d_in[10];
  const float* ap   = (const float*)d_in[11];
  const float* temp = (const float*)d_in[12];
  const float* rq   = (const float*)d_in[13];
  const float* rk   = (const float*)d_in[14];
  const float* rv   = (const float*)d_in[15];
  const float* rg   = (const float*)d_in[16];
  const float* cq   = (const float*)d_in[17];
  const float* ck   = (const float*)d_in[18];
  const float* cv   = (const float*)d_in[19];
  const float* cg   = (const float*)d_in[20];
  const float* fw   = (const float*)d_in[21];
  const float* fb   = (const float*)d_in[22];
  float* out = (float*)d_out;

  const int TILES = (BATCH*NN)/TP;                 // 1152
  const int SM_C1 = (64*256 + 64*68)*4;            // 82944
  const int SM_C2 = (64*256 + 2*64*68)*4;          // 100352
  const int SM_AP = (64*256 + 64*36)*4;            // 74752
  const int SM_LA = 2*192*68*4;                    // 104448
  cudaFuncSetAttribute(k_conv1,  cudaFuncAttributeMaxDynamicSharedMemorySize, SM_C1);
  cudaFuncSetAttribute(k_conv2,  cudaFuncAttributeMaxDynamicSharedMemorySize, SM_C2);
  cudaFuncSetAttribute(k_convDI, cudaFuncAttributeMaxDynamicSharedMemorySize, SM_C2);
  cudaFuncSetAttribute(k_final3, cudaFuncAttributeMaxDynamicSharedMemorySize, SM_C1);
  cudaFuncSetAttribute(k_apply_t,cudaFuncAttributeMaxDynamicSharedMemorySize, SM_AP);
  cudaFuncSetAttribute(k_lineattn,cudaFuncAttributeMaxDynamicSharedMemorySize, SM_LA);

  // t = pw(x); gelu(dw(t)+b); x1 = conv2(u)+b2 + conv0(x)+b0
  k_conv1<<<TILES,256,SM_C1>>>(x, -1, nullptr, 0, pw_w, 64, nullptr, 0);
  k_dwgelu<<<NELEM/256,256>>>(0, 1, dw_w, dw_b);
  k_convDI<<<TILES,256,SM_C2>>>(1, x, 2, c2w, c2b, c0w, c0b);

  // channel attention -> out1 (slice 7)
  k_conv2<<<TILES,256,SM_C2>>>(2, 3, 4, aq, ak);
  k_conv1<<<TILES,256,SM_C1>>>(nullptr, 2, nullptr, 5, av, 64, nullptr, 0);
  k_gram<<<512,256>>>(3, 4);
  k_attnsoft<<<8,1024>>>(temp);
  k_apply_t<<<TILES,256,SM_AP>>>(5, 6);
  k_conv1<<<TILES,256,SM_C1>>>(nullptr, 6, nullptr, 7, ap, 64, nullptr, 0);

  // row attention -> out2 (slice 8); rv+cv fused (both read out1)
  k_conv2<<<TILES,256,SM_C2>>>(2, 3, 4, rq, rk);
  k_conv2<<<TILES,256,SM_C2>>>(7, 5, 9, rv, cv);
  k_lineattn<<<768,192,SM_LA>>>(3, 4, 5, 2, 8, rg);

  // col attention -> out3 (slice 9 at the end)
  k_conv2<<<TILES,256,SM_C2>>>(2, 3, 4, cq, ck);
  dim3 tg(6,6,BATCH*CC), tb(32,8);
  k_transpose<<<tg,tb>>>(3, 0);
  k_transpose<<<tg,tb>>>(4, 1);
  k_transpose<<<tg,tb>>>(9, 6);
  k_transpose<<<tg,tb>>>(2, 10);
  k_lineattn<<<768,192,SM_LA>>>(0, 1, 6, 10, 3, cg);
  k_transpose<<<tg,tb>>>(3, 9);

  // fuse
  k_final3<<<TILES,256,SM_C1>>>(7, 8, 9, fw, fb, out);
}

// round 10
// speedup vs baseline: 1.0715x; 1.0715x over previous
#include <cuda_runtime.h>
#include <math.h>

#define BATCH 4
#define CC 64
#define HH 192
#define WW 192
#define NN (HH*WW)
#define NELEM (BATCH*CC*NN)
#define TP 128

__device__ float g_scratch[(size_t)11 * NELEM];
__device__ float g_gram[512*1024];
__device__ float g_normp[512*64];
__device__ float g_attnw[8*1024];

typedef unsigned long long u64;

__device__ __forceinline__ u64 pack2(float a, float b){
  u64 r;
  asm("mov.b64 %0, {%1,%2};" : "=l"(r) : "r"(__float_as_uint(a)), "r"(__float_as_uint(b)));
  return r;
}
__device__ __forceinline__ void unpack2(u64 v, float &a, float &b){
  unsigned lo, hi;
  asm("mov.b64 {%0,%1}, %2;" : "=r"(lo), "=r"(hi) : "l"(v));
  a = __uint_as_float(lo); b = __uint_as_float(hi);
}
__device__ __forceinline__ void ffma2(u64 &d, u64 a, u64 b){
  asm("fma.rn.f32x2 %0, %1, %2, %0;" : "+l"(d) : "l"(a), "l"(b));
}
__device__ __forceinline__ float gelu_f(float x){
  return 0.5f*x*(1.0f + erff(x*0.70710678118654752f));
}

// one k-step (R5 layout): x as float4 + register splats, w as 2x LDS.128 broadcast
#define CONV_STEP(ACC, XROW, WROW, K)                                           \
  {                                                                             \
    float4 xv = *(const float4*)((XROW) + (K)*TP);                              \
    u64 s0 = pack2(xv.x, xv.x), s1 = pack2(xv.y, xv.y);                         \
    u64 s2 = pack2(xv.z, xv.z), s3 = pack2(xv.w, xv.w);                         \
    ulonglong2 wv0 = *(const ulonglong2*)((WROW) + (K)*68);                     \
    ulonglong2 wv1 = *(const ulonglong2*)((WROW) + (K)*68 + 4);                 \
    ffma2(ACC[0],  wv0.x, s0); ffma2(ACC[1],  wv0.x, s1);                       \
    ffma2(ACC[2],  wv0.x, s2); ffma2(ACC[3],  wv0.x, s3);                       \
    ffma2(ACC[4],  wv0.y, s0); ffma2(ACC[5],  wv0.y, s1);                       \
    ffma2(ACC[6],  wv0.y, s2); ffma2(ACC[7],  wv0.y, s3);                       \
    ffma2(ACC[8],  wv1.x, s0); ffma2(ACC[9],  wv1.x, s1);                       \
    ffma2(ACC[10], wv1.x, s2); ffma2(ACC[11], wv1.x, s3);                       \
    ffma2(ACC[12], wv1.y, s0); ffma2(ACC[13], wv1.y, s1);                       \
    ffma2(ACC[14], wv1.y, s2); ffma2(ACC[15], wv1.y, s3);                       \
  }

// epilogue: acc[pp*4+px] = (y[o=base+2pp], y[o=base+2pp+1]) at pixel px
__device__ __forceinline__ void store8(
    u64* acc, float* yb, int obase, int lane,
    const float* bias, const float* bias2, int do_gelu)
{
  #pragma unroll
  for (int pp = 0; pp < 4; pp++){
    float lo0,hi0,lo1,hi1,lo2,hi2,lo3,hi3;
    unpack2(acc[pp*4+0], lo0, hi0);
    unpack2(acc[pp*4+1], lo1, hi1);
    unpack2(acc[pp*4+2], lo2, hi2);
    unpack2(acc[pp*4+3], lo3, hi3);
    int o = obase + 2*pp;
    float b0 = bias ? bias[o] : 0.f;
    float b1 = bias ? bias[o+1] : 0.f;
    if (bias2){ b0 += bias2[o]; b1 += bias2[o+1]; }
    lo0+=b0; lo1+=b0; lo2+=b0; lo3+=b0;
    hi0+=b1; hi1+=b1; hi2+=b1; hi3+=b1;
    if (do_gelu){
      lo0=gelu_f(lo0); lo1=gelu_f(lo1); lo2=gelu_f(lo2); lo3=gelu_f(lo3);
      hi0=gelu_f(hi0); hi1=gelu_f(hi1); hi2=gelu_f(hi2); hi3=gelu_f(hi3);
    }
    *(float4*)(yb + (size_t)o*NN     + lane*4) = make_float4(lo0,lo1,lo2,lo3);
    *(float4*)(yb + (size_t)(o+1)*NN + lane*4) = make_float4(hi0,hi1,hi2,hi3);
  }
}

// ================= single-matrix conv1x1 (64->64) =================
__global__ void __launch_bounds__(256,3) k_conv1(
    const float* __restrict__ ext_in, int in_slice,
    float* __restrict__ ext_out, int out_slice,
    const float* __restrict__ w, int ldw,
    const float* __restrict__ bias, int do_gelu)
{
  extern __shared__ float sm[];
  float* xs = sm;              // [64][128]
  float* ws = sm + 64*TP;      // [64][68]  ws[c*68+o] = w[o][c]
  int tid = threadIdx.x, lane = tid & 31, wid = tid >> 5;
  const float* xin = (in_slice >= 0) ? g_scratch + (size_t)in_slice*NELEM : ext_in;
  float* yout = (out_slice >= 0) ? g_scratch + (size_t)out_slice*NELEM : ext_out;
  for (int i = tid; i < 4096; i += 256){
    int c = i & 63, o = i >> 6;
    ws[c*68 + o] = w[o*ldw + c];
  }
  int p0 = blockIdx.x * TP;
  int b = p0 / NN, n0 = p0 - b*NN;
  const float* xb = xin + (size_t)b*(CC*NN) + n0;
  for (int i = tid; i < 2048; i += 256){
    int c = i >> 5, q = i & 31;
    *(float4*)(xs + c*TP + q*4) = *(const float4*)(xb + (size_t)c*NN + q*4);
  }
  __syncthreads();
  u64 acc[16];
  u64 z = pack2(0.f, 0.f);
  #pragma unroll
  for (int i = 0; i < 16; i++) acc[i] = z;
  const float* xrow = xs + lane*4;
  const float* wrow = ws + wid*8;
  #pragma unroll 8
  for (int k = 0; k < 64; k++) CONV_STEP(acc, xrow, wrow, k);
  float* yb = yout + (size_t)b*(CC*NN) + n0;
  store8(acc, yb, wid*8, lane, bias, nullptr, do_gelu);
}

// ================= dual-output conv1x1 =================
__global__ void __launch_bounds__(256,2) k_conv2(
    int in_slice, int outA, int outB,
    const float* __restrict__ wA, const float* __restrict__ wB)
{
  extern __shared__ float sm[];
  float* xs  = sm;               // [64][128]
  float* wsA = sm + 64*TP;       // [64][68]
  float* wsB = wsA + 64*68;
  int tid = threadIdx.x, lane = tid & 31, wid = tid >> 5;
  for (int i = tid; i < 4096; i += 256){
    int c = i & 63, o = i >> 6;
    wsA[c*68 + o] = wA[o*64 + c];
    wsB[c*68 + o] = wB[o*64 + c];
  }
  int p0 = blockIdx.x * TP;
  int b = p0 / NN, n0 = p0 - b*NN;
  const float* xb = g_scratch + (size_t)in_slice*NELEM + (size_t)b*(CC*NN) + n0;
  for (int i = tid; i < 2048; i += 256){
    int c = i >> 5, q = i & 31;
    *(float4*)(xs + c*TP + q*4) = *(const float4*)(xb + (size_t)c*NN + q*4);
  }
  __syncthreads();
  u64 accA[16], accB[16];
  u64 z = pack2(0.f, 0.f);
  #pragma unroll
  for (int i = 0; i < 16; i++){ accA[i] = z; accB[i] = z; }
  const float* xrow = xs + lane*4;
  const float* wra = wsA + wid*8;
  const float* wrb = wsB + wid*8;
  #pragma unroll 4
  for (int k = 0; k < 64; k++){
    CONV_STEP(accA, xrow, wra, k);
    CONV_STEP(accB, xrow, wrb, k);
  }
  size_t boff = (size_t)b*(CC*NN) + n0;
  store8(accA, g_scratch + (size_t)outA*NELEM + boff, wid*8, lane, nullptr, nullptr, 0);
  store8(accB, g_scratch + (size_t)outB*NELEM + boff, wid*8, lane, nullptr, nullptr, 0);
}

// ================= dual-input conv1x1: y = wA@inA + bA + wB@inB + bB =================
__global__ void __launch_bounds__(256,2) k_convDI(
    int inA_slice, const float* __restrict__ extB, int out_slice,
    const float* __restrict__ wA, const float* __restrict__ bA,
    const float* __restrict__ wB, const float* __restrict__ bB)
{
  extern __shared__ float sm[];
  float* xsA = sm;               // [64][128]
  float* xsB = xsA + 64*TP;
  float* wsA = xsB + 64*TP;      // [64][68]
  float* wsB = wsA + 64*68;
  int tid = threadIdx.x, lane = tid & 31, wid = tid >> 5;
  for (int i = tid; i < 4096; i += 256){
    int c = i & 63, o = i >> 6;
    wsA[c*68 + o] = wA[o*64 + c];
    wsB[c*68 + o] = wB[o*64 + c];
  }
  int p0 = blockIdx.x * TP;
  int b = p0 / NN, n0 = p0 - b*NN;
  size_t boff = (size_t)b*(CC*NN) + n0;
  const float* xa = g_scratch + (size_t)inA_slice*NELEM + boff;
  const float* xbp = extB + boff;
  for (int i = tid; i < 2048; i += 256){
    int c = i >> 5, q = i & 31;
    *(float4*)(xsA + c*TP + q*4) = *(const float4*)(xa  + (size_t)c*NN + q*4);
    *(float4*)(xsB + c*TP + q*4) = *(const float4*)(xbp + (size_t)c*NN + q*4);
  }
  __syncthreads();
  u64 acc[16];
  u64 z = pack2(0.f, 0.f);
  #pragma unroll
  for (int i = 0; i < 16; i++) acc[i] = z;
  const float* xra = xsA + lane*4;
  const float* xrb = xsB + lane*4;
  const float* wra = wsA + wid*8;
  const float* wrb = wsB + wid*8;
  #pragma unroll 4
  for (int k = 0; k < 64; k++){
    CONV_STEP(acc, xra, wra, k);
    CONV_STEP(acc, xrb, wrb, k);
  }
  store8(acc, g_scratch + (size_t)out_slice*NELEM + boff, wid*8, lane, bA, bB, 0);
}

// ================= final conv 192->64 (3 slices) + GELU =================
__global__ void __launch_bounds__(256,2) k_final3(
    int s1, int s2, int s3,
    const float* __restrict__ w, const float* __restrict__ bias,
    float* __restrict__ out)
{
  extern __shared__ float sm[];
  float* xs = sm;              // [64][128]
  float* ws = sm + 64*TP;      // [192][68]
  int tid = threadIdx.x, lane = tid & 31, wid = tid >> 5;
  for (int i = tid; i < 12288; i += 256){
    int o = i / 192, c = i - o*192;
    ws[c*68 + o] = w[o*192 + c];
  }
  int p0 = blockIdx.x * TP;
  int b = p0 / NN, n0 = p0 - b*NN;
  size_t boff = (size_t)b*(CC*NN) + n0;
  u64 acc[16];
  u64 z = pack2(0.f, 0.f);
  #pragma unroll
  for (int i = 0; i < 16; i++) acc[i] = z;
  const float* xrow = xs + lane*4;
  int slices[3] = {s1, s2, s3};
  for (int p = 0; p < 3; p++){
    const float* xb = g_scratch + (size_t)slices[p]*NELEM + boff;
    __syncthreads();
    for (int i = tid; i < 2048; i += 256){
      int c = i >> 5, q = i & 31;
      *(float4*)(xs + c*TP + q*4) = *(const float4*)(xb + (size_t)c*NN + q*4);
    }
    __syncthreads();
    const float* wrow = ws + (p*64)*68 + wid*8;
    #pragma unroll 8
    for (int k = 0; k < 64; k++) CONV_STEP(acc, xrow, wrow, k);
  }
  store8(acc, out + boff, wid*8, lane, bias, nullptr, 1);
}

// ================= channel-attention apply (block-diag 2x 32x32) =================
__global__ void __launch_bounds__(256,3) k_apply_t(int v_slice, int out_slice)
{
  extern __shared__ float sm[];
  float* xs = sm;             // [64][128]
  float* ws = sm + 64*TP;     // [2*32][36] : ws[(g*32+k)*36 + o] = attn[b,g,o,k]
  int tid = threadIdx.x, lane = tid & 31, wid = tid >> 5;
  int p0 = blockIdx.x * TP;
  int b = p0 / NN, n0 = p0 - b*NN;
  for (int i = tid; i < 2048; i += 256){
    int g = i >> 10, rem = i & 1023;
    int o = rem >> 5, k = rem & 31;
    ws[(g*32 + k)*36 + o] = g_attnw[(size_t)(b*2+g)*1024 + o*32 + k];
  }
  const float* xb = g_scratch + (size_t)v_slice*NELEM + (size_t)b*(CC*NN) + n0;
  for (int i = tid; i < 2048; i += 256){
    int c = i >> 5, q = i & 31;
    *(float4*)(xs + c*TP + q*4) = *(const float4*)(xb + (size_t)c*NN + q*4);
  }
  __syncthreads();
  int g = wid >> 2;
  int ow = (wid & 3) * 8;
  u64 acc[16];
  u64 z = pack2(0.f, 0.f);
  #pragma unroll
  for (int i = 0; i < 16; i++) acc[i] = z;
  const float* xrow = xs + g*32*TP + lane*4;
  const float* wrow0 = ws + g*32*36 + ow;
  #pragma unroll 8
  for (int k = 0; k < 32; k++){
    float4 xv = *(const float4*)(xrow + k*TP);
    u64 s0 = pack2(xv.x, xv.x), s1 = pack2(xv.y, xv.y);
    u64 s2 = pack2(xv.z, xv.z), s3 = pack2(xv.w, xv.w);
    ulonglong2 wv0  = *(const ulonglong2*)(wrow0 + k*36);
    ulonglong2 wv1  = *(const ulonglong2*)(wrow0 + k*36 + 4);
    ffma2(acc[0],  wv0.x, s0); ffma2(acc[1],  wv0.x, s1);
    ffma2(acc[2],  wv0.x, s2); ffma2(acc[3],  wv0.x, s3);
    ffma2(acc[4],  wv0.y, s0); ffma2(acc[5],  wv0.y, s1);
    ffma2(acc[6],  wv0.y, s2); ffma2(acc[7],  wv0.y, s3);
    ffma2(acc[8],  wv1.x, s0); ffma2(acc[9],  wv1.x, s1);
    ffma2(acc[10], wv1.x, s2); ffma2(acc[11], wv1.x, s3);
    ffma2(acc[12], wv1.y, s0); ffma2(acc[13], wv1.y, s1);
    ffma2(acc[14], wv1.y, s2); ffma2(acc[15], wv1.y, s3);
  }
  float* yb = g_scratch + (size_t)out_slice*NELEM + (size_t)b*(CC*NN) + n0;
  store8(acc, yb, g*32 + ow, lane, nullptr, nullptr, 0);
}

// ================= depthwise 3x3 + bias + exact GELU =================
__global__ void __launch_bounds__(256) k_dwgelu(
    int in_slice, int out_slice,
    const float* __restrict__ dw_w, const float* __restrict__ dw_b)
{
  int e = blockIdx.x*256 + threadIdx.x;
  const float* tin = g_scratch + (size_t)in_slice*NELEM;
  int n  = e % NN;
  int bc = e / NN;
  int c  = bc & 63;
  int h = n / WW, w = n - h*WW;
  const float* plane = tin + (size_t)bc*NN;
  float s = dw_b[c];
  #pragma unroll
  for (int ky = 0; ky < 3; ky++){
    int hh = h + ky - 1;
    if ((unsigned)hh >= (unsigned)HH) continue;
    #pragma unroll
    for (int kx = 0; kx < 3; kx++){
      int wx = w + kx - 1;
      if ((unsigned)wx >= (unsigned)WW) continue;
      s += dw_w[c*9 + ky*3 + kx] * plane[hh*WW + wx];
    }
  }
  g_scratch[(size_t)out_slice*NELEM + e] = gelu_f(s);
}

// ================= split-K gram + norms =================
__global__ void __launch_bounds__(256) k_gram(int q_slice, int k_slice)
{
  int blk = blockIdx.x;
  int s  = blk & 63;
  int bg = blk >> 6;
  int g = bg & 1, b = bg >> 1;
  int n0 = s * 576;
  const float* qb = g_scratch + (size_t)q_slice*NELEM + (size_t)(b*64 + g*32)*NN;
  const float* kb = g_scratch + (size_t)k_slice*NELEM + (size_t)(b*64 + g*32)*NN;
  __shared__ float qs[32][65];
  __shared__ float ks[32][65];
  int t = threadIdx.x;
  int i = t & 31, jb = t >> 5;
  float acc[4] = {0.f,0.f,0.f,0.f};
  float nacc = 0.f;
  for (int ch = 0; ch < 9; ch++){
    int nb = n0 + ch*64;
    __syncthreads();
    for (int idx = t; idx < 2048; idx += 256){
      int r = idx >> 6, nn = idx & 63;
      qs[r][nn] = qb[(size_t)r*NN + nb + nn];
      ks[r][nn] = kb[(size_t)r*NN + nb + nn];
    }
    __syncthreads();
    #pragma unroll 8
    for (int nn = 0; nn < 64; nn++){
      float qv = qs[i][nn];
      acc[0] += qv * ks[jb*4+0][nn];
      acc[1] += qv * ks[jb*4+1][nn];
      acc[2] += qv * ks[jb*4+2][nn];
      acc[3] += qv * ks[jb*4+3][nn];
    }
    if (t < 32){
      #pragma unroll 8
      for (int nn = 0; nn < 64; nn++){ float v = qs[t][nn]; nacc += v*v; }
    } else if (t < 64){
      int r = t - 32;
      #pragma unroll 8
      for (int nn = 0; nn < 64; nn++){ float v = ks[r][nn]; nacc += v*v; }
    }
  }
  float* Gp = g_gram + (size_t)blk*1024;
  #pragma unroll
  for (int jj = 0; jj < 4; jj++) Gp[i*32 + jb*4 + jj] = acc[jj];
  if (t < 64) g_normp[(size_t)blk*64 + t] = nacc;
}

// ================= gram finalize + softmax =================
__global__ void __launch_bounds__(1024) k_attnsoft(const float* __restrict__ temperature)
{
  int bg = blockIdx.x;
  int g = bg & 1;
  int t = threadIdx.x;
  int i = t >> 5, j = t & 31;
  __shared__ float nq[32], nk[32];
  if (t < 64){
    float s = 0.f;
    for (int ss = 0; ss < 64; ss++) s += g_normp[(size_t)(bg*64 + ss)*64 + t];
    float nv = fmaxf(sqrtf(s), 1e-12f);
    if (t < 32) nq[t] = nv; else nk[t-32] = nv;
  }
  float G = 0.f;
  for (int ss = 0; ss < 64; ss++) G += g_gram[(size_t)(bg*64 + ss)*1024 + t];
  __syncthreads();
  float logit = G / (nq[i]*nk[j]) * temperature[g];
  float m = logit;
  #pragma unroll
  for (int o = 16; o > 0; o >>= 1) m = fmaxf(m, __shfl_xor_sync(0xffffffffu, m, o));
  float e = __expf(logit - m);
  float ssum = e;
  #pragma unroll
  for (int o = 16; o > 0; o >>= 1) ssum += __shfl_xor_sync(0xffffffffu, ssum, o);
  g_attnw[(size_t)bg*1024 + t] = e / ssum;
}

// ================= line attention, split-j across two 192-thread groups =================
// grp0: j in [0,96), grp1: [96,192). Partials combined via smem (Ksh reused).
__global__ void __launch_bounds__(384, 1) k_lineattn(
    int q_slice, int k_slice, int v_slice, int x_slice, int out_slice,
    const float* __restrict__ gamma_p)
{
  extern __shared__ float smem[];
  float* Ksh = smem;                 // [192][68], j-major
  float* Vsh = smem + 192*68;
  int blk = blockIdx.x;
  int h = blk % HH;
  int b = blk / HH;
  size_t base = (size_t)b*(CC*NN) + (size_t)h*WW;
  const float* Qb = g_scratch + (size_t)q_slice*NELEM + base;
  const float* Kb = g_scratch + (size_t)k_slice*NELEM + base;
  const float* Vb = g_scratch + (size_t)v_slice*NELEM + base;
  float* Ob = g_scratch + (size_t)out_slice*NELEM + base;
  int t = threadIdx.x;
  int pix = t % 192;
  int grp = t / 192;
  for (int idx = t; idx < 64*192; idx += 384){
    int c = idx / 192;
    int j = idx - c*192;
    Ksh[j*68 + c] = Kb[(size_t)c*NN + j];
    Vsh[j*68 + c] = Vb[(size_t)c*NN + j];
  }
  u64 q2[32];
  #pragma unroll
  for (int cc = 0; cc < 32; cc++)
    q2[cc] = pack2(Qb[(size_t)(2*cc)*NN + pix], Qb[(size_t)(2*cc+1)*NN + pix]);
  __syncthreads();
  u64 z = pack2(0.f, 0.f);
  u64 acc[32];
  #pragma unroll
  for (int cc = 0; cc < 32; cc++) acc[cc] = z;
  float l = 0.f;
  int j0 = grp * 96;
  #pragma unroll 2
  for (int j = j0; j < j0 + 96; j++){
    const ulonglong2* kr = (const ulonglong2*)(Ksh + j*68);
    u64 a0 = z, a1 = z, a2 = z, a3 = z;
    #pragma unroll
    for (int cc = 0; cc < 16; cc += 2){
      ulonglong2 kv0 = kr[cc];
      ulonglong2 kv1 = kr[cc+1];
      ffma2(a0, q2[2*cc+0], kv0.x);
      ffma2(a1, q2[2*cc+1], kv0.y);
      ffma2(a2, q2[2*cc+2], kv1.x);
      ffma2(a3, q2[2*cc+3], kv1.y);
    }
    float x0,y0,x1,y1,x2,y2,x3,y3;
    unpack2(a0,x0,y0); unpack2(a1,x1,y1); unpack2(a2,x2,y2); unpack2(a3,x3,y3);
    float s = ((x0+y0)+(x1+y1)) + ((x2+y2)+(x3+y3));
    float p = __expf(s);
    l += p;
    u64 ps = pack2(p, p);
    const ulonglong2* vr = (const ulonglong2*)(Vsh + j*68);
    #pragma unroll
    for (int cc = 0; cc < 16; cc++){
      ulonglong2 vv = vr[cc];
      ffma2(acc[2*cc],   ps, vv.x);
      ffma2(acc[2*cc+1], ps, vv.y);
    }
  }
  __syncthreads();                 // everyone done reading Ksh/Vsh for its range
  if (grp == 1){
    float* dst = Ksh + pix*68;     // reuse Ksh as partial buffer: 64 acc floats + l
    #pragma unroll
    for (int cc = 0; cc < 32; cc++) *(u64*)(dst + 2*cc) = acc[cc];
    dst[64] = l;
  }
  __syncthreads();
  if (grp == 0){
    const float* src = Ksh + pix*68;
    l += src[64];
    float gam = gamma_p[0] / l;
    const float* Xb = (x_slice >= 0) ? g_scratch + (size_t)x_slice*NELEM + base : nullptr;
    #pragma unroll
    for (int cc = 0; cc < 32; cc++){
      float a0, a1; unpack2(acc[cc], a0, a1);
      float2 o2 = *(const float2*)(src + 2*cc);
      a0 = gam*(a0 + o2.x);
      a1 = gam*(a1 + o2.y);
      if (Xb){
        a0 += Xb[(size_t)(2*cc)*NN + pix];
        a1 += Xb[(size_t)(2*cc+1)*NN + pix];
      }
      Ob[(size_t)(2*cc)*NN + pix]   = a0;
      Ob[(size_t)(2*cc+1)*NN + pix] = a1;
    }
  }
}

// ================= per-plane 192x192 transpose (optional fused add) =================
__global__ void k_transpose(int in_slice, int out_slice, int add_slice)
{
  __shared__ float tile[32][33];
  const float* in = g_scratch + (size_t)in_slice*NELEM + (size_t)blockIdx.z*NN;
  float* out      = g_scratch + (size_t)out_slice*NELEM + (size_t)blockIdx.z*NN;
  const float* ad = (add_slice >= 0) ? g_scratch + (size_t)add_slice*NELEM + (size_t)blockIdx.z*NN : nullptr;
  int x0 = blockIdx.x*32, y0 = blockIdx.y*32;
  int tx = threadIdx.x, ty = threadIdx.y;
  #pragma unroll
  for (int k = 0; k < 32; k += 8)
    tile[ty+k][tx] = in[(size_t)(y0+ty+k)*WW + x0+tx];
  __syncthreads();
  #pragma unroll
  for (int k = 0; k < 32; k += 8){
    float v = tile[tx][ty+k];
    size_t oidx = (size_t)(x0+ty+k)*HH + y0+tx;
    if (ad) v += ad[oidx];
    out[oidx] = v;
  }
}

extern "C" void kernel_launch(void* const* d_in, const int* in_sizes, int n_in,
                              void* d_out, int out_size)
{
  const float* x    = (const float*)d_in[0];
  const float* pw_w = (const float*)d_in[1];
  const float* dw_w = (const float*)d_in[2];
  const float* dw_b = (const float*)d_in[3];
  const float* c2w  = (const float*)d_in[4];
  const float* c2b  = (const float*)d_in[5];
  const float* c0w  = (const float*)d_in[6];
  const float* c0b  = (const float*)d_in[7];
  const float* aq   = (const float*)d_in[8];
  const float* ak   = (const float*)d_in[9];
  const float* av   = (const float*)d_in[10];
  const float* ap   = (const float*)d_in[11];
  const float* temp = (const float*)d_in[12];
  const float* rq   = (const float*)d_in[13];
  const float* rk   = (const float*)d_in[14];
  const float* rv   = (const float*)d_in[15];
  const float* rg   = (const float*)d_in[16];
  const float* cq   = (const float*)d_in[17];
  const float* ck   = (const float*)d_in[18];
  const float* cv   = (const float*)d_in[19];
  const float* cg   = (const float*)d_in[20];
  const float* fw   = (const float*)d_in[21];
  const float* fb   = (const float*)d_in[22];
  float* out = (float*)d_out;

  const int TILES = (BATCH*NN)/TP;                 // 1152
  const int SM_C1 = (64*TP + 64*68)*4;             // 50176
  const int SM_C2 = (64*TP + 2*64*68)*4;           // 67584
  const int SM_DI = (2*64*TP + 2*64*68)*4;         // 100352
  const int SM_F3 = (64*TP + 192*68)*4;            // 84992
  const int SM_AP = (64*TP + 64*36)*4;             // 41984
  const int SM_LA = 2*192*68*4;                    // 104448
  cudaFuncSetAttribute(k_conv1,  cudaFuncAttributeMaxDynamicSharedMemorySize, SM_C1);
  cudaFuncSetAttribute(k_conv2,  cudaFuncAttributeMaxDynamicSharedMemorySize, SM_C2);
  cudaFuncSetAttribute(k_convDI, cudaFuncAttributeMaxDynamicSharedMemorySize, SM_DI);
  cudaFuncSetAttribute(k_final3, cudaFuncAttributeMaxDynamicSharedMemorySize, SM_F3);
  cudaFuncSetAttribute(k_apply_t,cudaFuncAttributeMaxDynamicSharedMemorySize, SM_AP);
  cudaFuncSetAttribute(k_lineattn,cudaFuncAttributeMaxDynamicSharedMemorySize, SM_LA);

  // t = pw(x); gelu(dw(t)+b); x1 = conv2(u)+b2 + conv0(x)+b0
  k_conv1<<<TILES,256,SM_C1>>>(x, -1, nullptr, 0, pw_w, 64, nullptr, 0);
  k_dwgelu<<<NELEM/256,256>>>(0, 1, dw_w, dw_b);
  k_convDI<<<TILES,256,SM_DI>>>(1, x, 2, c2w, c2b, c0w, c0b);

  // channel attention -> out1 (slice 7)
  k_conv2<<<TILES,256,SM_C2>>>(2, 3, 4, aq, ak);
  k_conv1<<<TILES,256,SM_C1>>>(nullptr, 2, nullptr, 5, av, 64, nullptr, 0);
  k_gram<<<512,256>>>(3, 4);
  k_attnsoft<<<8,1024>>>(temp);
  k_apply_t<<<TILES,256,SM_AP>>>(5, 6);
  k_conv1<<<TILES,256,SM_C1>>>(nullptr, 6, nullptr, 7, ap, 64, nullptr, 0);

  // row attention -> out2 (slice 8); rv+cv fused (both read out1)
  k_conv2<<<TILES,256,SM_C2>>>(2, 3, 4, rq, rk);
  k_conv2<<<TILES,256,SM_C2>>>(7, 5, 9, rv, cv);
  k_lineattn<<<768,384,SM_LA>>>(3, 4, 5, 2, 8, rg);

  // col attention -> out3 (slice 9)
  k_conv2<<<TILES,256,SM_C2>>>(2, 3, 4, cq, ck);
  dim3 tg(6,6,BATCH*CC), tb(32,8);
  k_transpose<<<tg,tb>>>(3, 0, -1);
  k_transpose<<<tg,tb>>>(4, 1, -1);
  k_transpose<<<tg,tb>>>(9, 6, -1);
  k_lineattn<<<768,384,SM_LA>>>(0, 1, 6, -1, 3, cg);   // attn-only out3^T
  k_transpose<<<tg,tb>>>(3, 9, 2);                     // out3 = (out3^T)^T + x1

  // fuse
  k_final3<<<TILES,256,SM_F3>>>(7, 8, 9, fw, fb, out);
}

// round 13
// speedup vs baseline: 1.0783x; 1.0063x over previous
#include <cuda_runtime.h>
#include <math.h>

#define BATCH 4
#define CC 64
#define HH 192
#define WW 192
#define NN (HH*WW)
#define NELEM (BATCH*CC*NN)
#define TP 128

__device__ float g_scratch[(size_t)11 * NELEM];
__device__ float g_gram[512*1024];
__device__ float g_normp[512*64];
__device__ float g_attnw[8*1024];

typedef unsigned long long u64;

__device__ __forceinline__ u64 pack2(float a, float b){
  u64 r;
  asm("mov.b64 %0, {%1,%2};" : "=l"(r) : "r"(__float_as_uint(a)), "r"(__float_as_uint(b)));
  return r;
}
__device__ __forceinline__ void unpack2(u64 v, float &a, float &b){
  unsigned lo, hi;
  asm("mov.b64 {%0,%1}, %2;" : "=r"(lo), "=r"(hi) : "l"(v));
  a = __uint_as_float(lo); b = __uint_as_float(hi);
}
__device__ __forceinline__ void ffma2(u64 &d, u64 a, u64 b){
  asm("fma.rn.f32x2 %0, %1, %2, %0;" : "+l"(d) : "l"(a), "l"(b));
}
__device__ __forceinline__ float gelu_f(float x){
  return 0.5f*x*(1.0f + erff(x*0.70710678118654752f));
}

// ---- 16-out x 4-px k-step: acc[pair p (8) * 4 + px], 32 ffma2, 5 LDS.128 ----
#define STEP16x4(ACC, XROW, WROW, K, XSTRIDE)                                   \
  {                                                                             \
    float4 xv = *(const float4*)((XROW) + (size_t)(K)*(XSTRIDE));               \
    u64 s0 = pack2(xv.x, xv.x), s1 = pack2(xv.y, xv.y);                         \
    u64 s2 = pack2(xv.z, xv.z), s3 = pack2(xv.w, xv.w);                         \
    const float* wk = (WROW) + (K)*68;                                          \
    ulonglong2 w0 = *(const ulonglong2*)(wk);                                   \
    ulonglong2 w1 = *(const ulonglong2*)(wk + 4);                               \
    ulonglong2 w2 = *(const ulonglong2*)(wk + 8);                               \
    ulonglong2 w3 = *(const ulonglong2*)(wk + 12);                              \
    ffma2(ACC[0],  w0.x, s0); ffma2(ACC[1],  w0.x, s1);                         \
    ffma2(ACC[2],  w0.x, s2); ffma2(ACC[3],  w0.x, s3);                         \
    ffma2(ACC[4],  w0.y, s0); ffma2(ACC[5],  w0.y, s1);                         \
    ffma2(ACC[6],  w0.y, s2); ffma2(ACC[7],  w0.y, s3);                         \
    ffma2(ACC[8],  w1.x, s0); ffma2(ACC[9],  w1.x, s1);                         \
    ffma2(ACC[10], w1.x, s2); ffma2(ACC[11], w1.x, s3);                         \
    ffma2(ACC[12], w1.y, s0); ffma2(ACC[13], w1.y, s1);                         \
    ffma2(ACC[14], w1.y, s2); ffma2(ACC[15], w1.y, s3);                         \
    ffma2(ACC[16], w2.x, s0); ffma2(ACC[17], w2.x, s1);                         \
    ffma2(ACC[18], w2.x, s2); ffma2(ACC[19], w2.x, s3);                         \
    ffma2(ACC[20], w2.y, s0); ffma2(ACC[21], w2.y, s1);                         \
    ffma2(ACC[22], w2.y, s2); ffma2(ACC[23], w2.y, s3);                         \
    ffma2(ACC[24], w3.x, s0); ffma2(ACC[25], w3.x, s1);                         \
    ffma2(ACC[26], w3.x, s2); ffma2(ACC[27], w3.x, s3);                         \
    ffma2(ACC[28], w3.y, s0); ffma2(ACC[29], w3.y, s1);                         \
    ffma2(ACC[30], w3.y, s2); ffma2(ACC[31], w3.y, s3);                         \
  }

// ---- 16-out x 2-px k-step (one matrix): acc[p*2+px], 16 ffma2 ----
#define STEP16x2(ACC, S0, S1, WROW, K)                                          \
  {                                                                             \
    const float* wk = (WROW) + (K)*68;                                          \
    ulonglong2 w0 = *(const ulonglong2*)(wk);                                   \
    ulonglong2 w1 = *(const ulonglong2*)(wk + 4);                               \
    ulonglong2 w2 = *(const ulonglong2*)(wk + 8);                               \
    ulonglong2 w3 = *(const ulonglong2*)(wk + 12);                              \
    ffma2(ACC[0],  w0.x, S0); ffma2(ACC[1],  w0.x, S1);                         \
    ffma2(ACC[2],  w0.y, S0); ffma2(ACC[3],  w0.y, S1);                         \
    ffma2(ACC[4],  w1.x, S0); ffma2(ACC[5],  w1.x, S1);                         \
    ffma2(ACC[6],  w1.y, S0); ffma2(ACC[7],  w1.y, S1);                         \
    ffma2(ACC[8],  w2.x, S0); ffma2(ACC[9],  w2.x, S1);                         \
    ffma2(ACC[10], w2.y, S0); ffma2(ACC[11], w2.y, S1);                         \
    ffma2(ACC[12], w3.x, S0); ffma2(ACC[13], w3.x, S1);                         \
    ffma2(ACC[14], w3.y, S0); ffma2(ACC[15], w3.y, S1);                         \
  }

// store 16 outputs x 4 px
__device__ __forceinline__ void store16_4(
    u64* acc, float* yb, int obase, int pbase,
    const float* bias, const float* bias2, int do_gelu)
{
  #pragma unroll
  for (int p = 0; p < 8; p++){
    float lo0,hi0,lo1,hi1,lo2,hi2,lo3,hi3;
    unpack2(acc[p*4+0], lo0, hi0);
    unpack2(acc[p*4+1], lo1, hi1);
    unpack2(acc[p*4+2], lo2, hi2);
    unpack2(acc[p*4+3], lo3, hi3);
    int o = obase + 2*p;
    float b0 = bias ? bias[o] : 0.f;
    float b1 = bias ? bias[o+1] : 0.f;
    if (bias2){ b0 += bias2[o]; b1 += bias2[o+1]; }
    lo0+=b0; lo1+=b0; lo2+=b0; lo3+=b0;
    hi0+=b1; hi1+=b1; hi2+=b1; hi3+=b1;
    if (do_gelu){
      lo0=gelu_f(lo0); lo1=gelu_f(lo1); lo2=gelu_f(lo2); lo3=gelu_f(lo3);
      hi0=gelu_f(hi0); hi1=gelu_f(hi1); hi2=gelu_f(hi2); hi3=gelu_f(hi3);
    }
    *(float4*)(yb + (size_t)o*NN     + pbase) = make_float4(lo0,lo1,lo2,lo3);
    *(float4*)(yb + (size_t)(o+1)*NN + pbase) = make_float4(hi0,hi1,hi2,hi3);
  }
}

// store 16 outputs x 2 px
__device__ __forceinline__ void store16_2(
    u64* acc, float* yb, int obase, int pbase)
{
  #pragma unroll
  for (int p = 0; p < 8; p++){
    float lo0,hi0,lo1,hi1;
    unpack2(acc[p*2+0], lo0, hi0);
    unpack2(acc[p*2+1], lo1, hi1);
    int o = obase + 2*p;
    *(float2*)(yb + (size_t)o*NN     + pbase) = make_float2(lo0,lo1);
    *(float2*)(yb + (size_t)(o+1)*NN + pbase) = make_float2(hi0,hi1);
  }
}

// ================= single-matrix conv1x1: 256px x 64out, warp = 16out x 4px =================
__global__ void __launch_bounds__(256,2) k_convW1(
    const float* __restrict__ ext_in, int in_slice,
    float* __restrict__ ext_out, int out_slice,
    const float* __restrict__ w, int ldw,
    const float* __restrict__ bias, int do_gelu)
{
  extern __shared__ float sm[];
  float* xs = sm;              // [64][256]
  float* ws = sm + 64*256;     // [64][68]
  int tid = threadIdx.x, lane = tid & 31, wid = tid >> 5;
  int og = (wid & 3) * 16;
  int ph = wid >> 2;
  const float* xin = (in_slice >= 0) ? g_scratch + (size_t)in_slice*NELEM : ext_in;
  float* yout = (out_slice >= 0) ? g_scratch + (size_t)out_slice*NELEM : ext_out;
  for (int i = tid; i < 4096; i += 256){
    int c = i & 63, o = i >> 6;
    ws[c*68 + o] = w[o*ldw + c];
  }
  int p0 = blockIdx.x * 256;
  int b = p0 / NN, n0 = p0 - b*NN;
  const float* xb = xin + (size_t)b*(CC*NN) + n0;
  for (int i = tid; i < 4096; i += 256){
    int c = i >> 6, q = i & 63;
    *(float4*)(xs + c*256 + q*4) = *(const float4*)(xb + (size_t)c*NN + q*4);
  }
  __syncthreads();
  u64 acc[32];
  u64 z = pack2(0.f, 0.f);
  #pragma unroll
  for (int i = 0; i < 32; i++) acc[i] = z;
  const float* xrow = xs + ph*128 + lane*4;
  const float* wrow = ws + og;
  #pragma unroll 4
  for (int k = 0; k < 64; k++) STEP16x4(acc, xrow, wrow, k, 256);
  float* yb = yout + (size_t)b*(CC*NN) + n0;
  store16_4(acc, yb, og, ph*128 + lane*4, bias, nullptr, do_gelu);
}

// ================= dual-matrix conv1x1: 128px x 64out x 2 mats, warp = 16out x 2px =================
__global__ void __launch_bounds__(256,2) k_convW2(
    int in_slice, int outA, int outB,
    const float* __restrict__ wA, const float* __restrict__ wB)
{
  extern __shared__ float sm[];
  float* xs  = sm;               // [64][128]
  float* wsA = sm + 64*TP;       // [64][68]
  float* wsB = wsA + 64*68;
  int tid = threadIdx.x, lane = tid & 31, wid = tid >> 5;
  int og = (wid & 3) * 16;
  int ph = wid >> 2;
  for (int i = tid; i < 4096; i += 256){
    int c = i & 63, o = i >> 6;
    wsA[c*68 + o] = wA[o*64 + c];
    wsB[c*68 + o] = wB[o*64 + c];
  }
  int p0 = blockIdx.x * TP;
  int b = p0 / NN, n0 = p0 - b*NN;
  const float* xb = g_scratch + (size_t)in_slice*NELEM + (size_t)b*(CC*NN) + n0;
  for (int i = tid; i < 2048; i += 256){
    int c = i >> 5, q = i & 31;
    *(float4*)(xs + c*TP + q*4) = *(const float4*)(xb + (size_t)c*NN + q*4);
  }
  __syncthreads();
  u64 accA[16], accB[16];
  u64 z = pack2(0.f, 0.f);
  #pragma unroll
  for (int i = 0; i < 16; i++){ accA[i] = z; accB[i] = z; }
  const float* xrow = xs + ph*64 + lane*2;
  const float* wra = wsA + og;
  const float* wrb = wsB + og;
  #pragma unroll 4
  for (int k = 0; k < 64; k++){
    float2 xv = *(const float2*)(xrow + k*TP);
    u64 s0 = pack2(xv.x, xv.x), s1 = pack2(xv.y, xv.y);
    STEP16x2(accA, s0, s1, wra, k);
    STEP16x2(accB, s0, s1, wrb, k);
  }
  size_t boff = (size_t)b*(CC*NN) + n0;
  int pbase = ph*64 + lane*2;
  store16_2(accA, g_scratch + (size_t)outA*NELEM + boff, og, pbase);
  store16_2(accB, g_scratch + (size_t)outB*NELEM + boff, og, pbase);
}

// ================= dual-input conv1x1 (2 phases): y = wA@inA+bA + wB@inB+bB =================
__global__ void __launch_bounds__(256,2) k_convDI(
    int inA_slice, const float* __restrict__ extB, int out_slice,
    const float* __restrict__ wA, const float* __restrict__ bA,
    const float* __restrict__ wB, const float* __restrict__ bB)
{
  extern __shared__ float sm[];
  float* xs  = sm;               // [64][256]
  float* wsA = sm + 64*256;      // [64][68]
  float* wsB = wsA + 64*68;
  int tid = threadIdx.x, lane = tid & 31, wid = tid >> 5;
  int og = (wid & 3) * 16;
  int ph = wid >> 2;
  for (int i = tid; i < 4096; i += 256){
    int c = i & 63, o = i >> 6;
    wsA[c*68 + o] = wA[o*64 + c];
    wsB[c*68 + o] = wB[o*64 + c];
  }
  int p0 = blockIdx.x * 256;
  int b = p0 / NN, n0 = p0 - b*NN;
  size_t boff = (size_t)b*(CC*NN) + n0;
  u64 acc[32];
  u64 z = pack2(0.f, 0.f);
  #pragma unroll
  for (int i = 0; i < 32; i++) acc[i] = z;
  const float* xrow = xs + ph*128 + lane*4;
  // phase A
  {
    const float* xa = g_scratch + (size_t)inA_slice*NELEM + boff;
    for (int i = tid; i < 4096; i += 256){
      int c = i >> 6, q = i & 63;
      *(float4*)(xs + c*256 + q*4) = *(const float4*)(xa + (size_t)c*NN + q*4);
    }
    __syncthreads();
    const float* wrow = wsA + og;
    #pragma unroll 4
    for (int k = 0; k < 64; k++) STEP16x4(acc, xrow, wrow, k, 256);
    __syncthreads();
  }
  // phase B
  {
    const float* xbp = extB + boff;
    for (int i = tid; i < 4096; i += 256){
      int c = i >> 6, q = i & 63;
      *(float4*)(xs + c*256 + q*4) = *(const float4*)(xbp + (size_t)c*NN + q*4);
    }
    __syncthreads();
    const float* wrow = wsB + og;
    #pragma unroll 4
    for (int k = 0; k < 64; k++) STEP16x4(acc, xrow, wrow, k, 256);
  }
  store16_4(acc, g_scratch + (size_t)out_slice*NELEM + boff, og, ph*128 + lane*4, bA, bB, 0);
}

// ================= final conv 192->64 (3 phases) + GELU =================
__global__ void __launch_bounds__(256,2) k_final3(
    int s1, int s2, int s3,
    const float* __restrict__ w, const float* __restrict__ bias,
    float* __restrict__ out)
{
  extern __shared__ float sm[];
  float* xs = sm;              // [64][256]
  float* ws = sm + 64*256;     // [64][68] reloaded per phase
  int tid = threadIdx.x, lane = tid & 31, wid = tid >> 5;
  int og = (wid & 3) * 16;
  int ph = wid >> 2;
  int p0 = blockIdx.x * 256;
  int b = p0 / NN, n0 = p0 - b*NN;
  size_t boff = (size_t)b*(CC*NN) + n0;
  u64 acc[32];
  u64 z = pack2(0.f, 0.f);
  #pragma unroll
  for (int i = 0; i < 32; i++) acc[i] = z;
  const float* xrow = xs + ph*128 + lane*4;
  const float* wrow = ws + og;
  int slices[3] = {s1, s2, s3};
  for (int p = 0; p < 3; p++){
    if (p) __syncthreads();
    for (int i = tid; i < 4096; i += 256){
      int c = i & 63, o = i >> 6;
      ws[c*68 + o] = w[o*192 + p*64 + c];
    }
    const float* xb = g_scratch + (size_t)slices[p]*NELEM + boff;
    for (int i = tid; i < 4096; i += 256){
      int c = i >> 6, q = i & 63;
      *(float4*)(xs + c*256 + q*4) = *(const float4*)(xb + (size_t)c*NN + q*4);
    }
    __syncthreads();
    #pragma unroll 4
    for (int k = 0; k < 64; k++) STEP16x4(acc, xrow, wrow, k, 256);
  }
  store16_4(acc, out + boff, og, ph*128 + lane*4, bias, nullptr, 1);
}

// ================= channel-attention apply (block-diag 2x 32x32) =================
__global__ void __launch_bounds__(256,2) k_apply_t(int v_slice, int out_slice)
{
  extern __shared__ float sm[];
  float* xs = sm;             // [64][256]
  float* ws = sm + 64*256;    // [64][36] : ws[(g*32+k)*36 + o(<32)] = attn[b,g,o,k]
  int tid = threadIdx.x, lane = tid & 31, wid = tid >> 5;
  int og = (wid & 3) * 16;
  int ph = wid >> 2;
  int p0 = blockIdx.x * 256;
  int b = p0 / NN, n0 = p0 - b*NN;
  for (int i = tid; i < 2048; i += 256){
    int g = i >> 10, rem = i & 1023;
    int o = rem >> 5, k = rem & 31;
    ws[(g*32 + k)*36 + o] = g_attnw[(size_t)(b*2+g)*1024 + o*32 + k];
  }
  const float* xb = g_scratch + (size_t)v_slice*NELEM + (size_t)b*(CC*NN) + n0;
  for (int i = tid; i < 4096; i += 256){
    int c = i >> 6, q = i & 63;
    *(float4*)(xs + c*256 + q*4) = *(const float4*)(xb + (size_t)c*NN + q*4);
  }
  __syncthreads();
  int g = og >> 5;            // output group (0 or 1)
  int ow = og & 31;           // within-group output offset (FIX: was og — OOB smem read)
  u64 acc[32];
  u64 z = pack2(0.f, 0.f);
  #pragma unroll
  for (int i = 0; i < 32; i++) acc[i] = z;
  const float* xrow = xs + (size_t)g*32*256 + ph*128 + lane*4;
  const float* wrow = ws + (size_t)g*32*36 + ow;
  #pragma unroll 4
  for (int k = 0; k < 32; k++){
    float4 xv = *(const float4*)(xrow + k*256);
    u64 s0 = pack2(xv.x, xv.x), s1 = pack2(xv.y, xv.y);
    u64 s2 = pack2(xv.z, xv.z), s3 = pack2(xv.w, xv.w);
    const float* wk = wrow + k*36;
    ulonglong2 w0 = *(const ulonglong2*)(wk);
    ulonglong2 w1 = *(const ulonglong2*)(wk + 4);
    ulonglong2 w2 = *(const ulonglong2*)(wk + 8);
    ulonglong2 w3 = *(const ulonglong2*)(wk + 12);
    ffma2(acc[0],  w0.x, s0); ffma2(acc[1],  w0.x, s1);
    ffma2(acc[2],  w0.x, s2); ffma2(acc[3],  w0.x, s3);
    ffma2(acc[4],  w0.y, s0); ffma2(acc[5],  w0.y, s1);
    ffma2(acc[6],  w0.y, s2); ffma2(acc[7],  w0.y, s3);
    ffma2(acc[8],  w1.x, s0); ffma2(acc[9],  w1.x, s1);
    ffma2(acc[10], w1.x, s2); ffma2(acc[11], w1.x, s3);
    ffma2(acc[12], w1.y, s0); ffma2(acc[13], w1.y, s1);
    ffma2(acc[14], w1.y, s2); ffma2(acc[15], w1.y, s3);
    ffma2(acc[16], w2.x, s0); ffma2(acc[17], w2.x, s1);
    ffma2(acc[18], w2.x, s2); ffma2(acc[19], w2.x, s3);
    ffma2(acc[20], w2.y, s0); ffma2(acc[21], w2.y, s1);
    ffma2(acc[22], w2.y, s2); ffma2(acc[23], w2.y, s3);
    ffma2(acc[24], w3.x, s0); ffma2(acc[25], w3.x, s1);
    ffma2(acc[26], w3.x, s2); ffma2(acc[27], w3.x, s3);
    ffma2(acc[28], w3.y, s0); ffma2(acc[29], w3.y, s1);
    ffma2(acc[30], w3.y, s2); ffma2(acc[31], w3.y, s3);
  }
  float* yb = g_scratch + (size_t)out_slice*NELEM + (size_t)b*(CC*NN) + n0;
  store16_4(acc, yb, og, ph*128 + lane*4, nullptr, nullptr, 0);
}

// ================= depthwise 3x3 + bias + exact GELU =================
__global__ void __launch_bounds__(256) k_dwgelu(
    int in_slice, int out_slice,
    const float* __restrict__ dw_w, const float* __restrict__ dw_b)
{
  int e = blockIdx.x*256 + threadIdx.x;
  const float* tin = g_scratch + (size_t)in_slice*NELEM;
  int n  = e % NN;
  int bc = e / NN;
  int c  = bc & 63;
  int h = n / WW, w = n - h*WW;
  const float* plane = tin + (size_t)bc*NN;
  float s = dw_b[c];
  #pragma unroll
  for (int ky = 0; ky < 3; ky++){
    int hh = h + ky - 1;
    if ((unsigned)hh >= (unsigned)HH) continue;
    #pragma unroll
    for (int kx = 0; kx < 3; kx++){
      int wx = w + kx - 1;
      if ((unsigned)wx >= (unsigned)WW) continue;
      s += dw_w[c*9 + ky*3 + kx] * plane[hh*WW + wx];
    }
  }
  g_scratch[(size_t)out_slice*NELEM + e] = gelu_f(s);
}

// ================= split-K gram + norms =================
__global__ void __launch_bounds__(256) k_gram(int q_slice, int k_slice)
{
  int blk = blockIdx.x;
  int s  = blk & 63;
  int bg = blk >> 6;
  int g = bg & 1, b = bg >> 1;
  int n0 = s * 576;
  const float* qb = g_scratch + (size_t)q_slice*NELEM + (size_t)(b*64 + g*32)*NN;
  const float* kb = g_scratch + (size_t)k_slice*NELEM + (size_t)(b*64 + g*32)*NN;
  __shared__ float qs[32][65];
  __shared__ float ks[32][65];
  int t = threadIdx.x;
  int i = t & 31, jb = t >> 5;
  float acc[4] = {0.f,0.f,0.f,0.f};
  float nacc = 0.f;
  for (int ch = 0; ch < 9; ch++){
    int nb = n0 + ch*64;
    __syncthreads();
    for (int idx = t; idx < 2048; idx += 256){
      int r = idx >> 6, nn = idx & 63;
      qs[r][nn] = qb[(size_t)r*NN + nb + nn];
      ks[r][nn] = kb[(size_t)r*NN + nb + nn];
    }
    __syncthreads();
    #pragma unroll 8
    for (int nn = 0; nn < 64; nn++){
      float qv = qs[i][nn];
      acc[0] += qv * ks[jb*4+0][nn];
      acc[1] += qv * ks[jb*4+1][nn];
      acc[2] += qv * ks[jb*4+2][nn];
      acc[3] += qv * ks[jb*4+3][nn];
    }
    if (t < 32){
      #pragma unroll 8
      for (int nn = 0; nn < 64; nn++){ float v = qs[t][nn]; nacc += v*v; }
    } else if (t < 64){
      int r = t - 32;
      #pragma unroll 8
      for (int nn = 0; nn < 64; nn++){ float v = ks[r][nn]; nacc += v*v; }
    }
  }
  float* Gp = g_gram + (size_t)blk*1024;
  #pragma unroll
  for (int jj = 0; jj < 4; jj++) Gp[i*32 + jb*4 + jj] = acc[jj];
  if (t < 64) g_normp[(size_t)blk*64 + t] = nacc;
}

// ================= gram finalize + softmax =================
__global__ void __launch_bounds__(1024) k_attnsoft(const float* __restrict__ temperature)
{
  int bg = blockIdx.x;
  int g = bg & 1;
  int t = threadIdx.x;
  int i = t >> 5, j = t & 31;
  __shared__ float nq[32], nk[32];
  if (t < 64){
    float s = 0.f;
    for (int ss = 0; ss < 64; ss++) s += g_normp[(size_t)(bg*64 + ss)*64 + t];
    float nv = fmaxf(sqrtf(s), 1e-12f);
    if (t < 32) nq[t] = nv; else nk[t-32] = nv;
  }
  float G = 0.f;
  for (int ss = 0; ss < 64; ss++) G += g_gram[(size_t)(bg*64 + ss)*1024 + t];
  __syncthreads();
  float logit = G / (nq[i]*nk[j]) * temperature[g];
  float m = logit;
  #pragma unroll
  for (int o = 16; o > 0; o >>= 1) m = fmaxf(m, __shfl_xor_sync(0xffffffffu, m, o));
  float e = __expf(logit - m);
  float ssum = e;
  #pragma unroll
  for (int o = 16; o > 0; o >>= 1) ssum += __shfl_xor_sync(0xffffffffu, ssum, o);
  g_attnw[(size_t)bg*1024 + t] = e / ssum;
}

// ================= line attention, split-j across two 192-thread groups =================
__global__ void __launch_bounds__(384, 1) k_lineattn(
    int q_slice, int k_slice, int v_slice, int x_slice, int out_slice,
    const float* __restrict__ gamma_p)
{
  extern __shared__ float smem[];
  float* Ksh = smem;                 // [192][68], j-major
  float* Vsh = smem + 192*68;
  int blk = blockIdx.x;
  int h = blk % HH;
  int b = blk / HH;
  size_t base = (size_t)b*(CC*NN) + (size_t)h*WW;
  const float* Qb = g_scratch + (size_t)q_slice*NELEM + base;
  const float* Kb = g_scratch + (size_t)k_slice*NELEM + base;
  const float* Vb = g_scratch + (size_t)v_slice*NELEM + base;
  float* Ob = g_scratch + (size_t)out_slice*NELEM + base;
  int t = threadIdx.x;
  int pix = t % 192;
  int grp = t / 192;
  for (int idx = t; idx < 64*192; idx += 384){
    int c = idx / 192;
    int j = idx - c*192;
    Ksh[j*68 + c] = Kb[(size_t)c*NN + j];
    Vsh[j*68 + c] = Vb[(size_t)c*NN + j];
  }
  u64 q2[32];
  #pragma unroll
  for (int cc = 0; cc < 32; cc++)
    q2[cc] = pack2(Qb[(size_t)(2*cc)*NN + pix], Qb[(size_t)(2*cc+1)*NN + pix]);
  __syncthreads();
  u64 z = pack2(0.f, 0.f);
  u64 acc[32];
  #pragma unroll
  for (int cc = 0; cc < 32; cc++) acc[cc] = z;
  float l = 0.f;
  int j0 = grp * 96;
  #pragma unroll 2
  for (int j = j0; j < j0 + 96; j++){
    const ulonglong2* kr = (const ulonglong2*)(Ksh + j*68);
    u64 a0 = z, a1 = z, a2 = z, a3 = z;
    #pragma unroll
    for (int cc = 0; cc < 16; cc += 2){
      ulonglong2 kv0 = kr[cc];
      ulonglong2 kv1 = kr[cc+1];
      ffma2(a0, q2[2*cc+0], kv0.x);
      ffma2(a1, q2[2*cc+1], kv0.y);
      ffma2(a2, q2[2*cc+2], kv1.x);
      ffma2(a3, q2[2*cc+3], kv1.y);
    }
    float x0,y0,x1,y1,x2,y2,x3,y3;
    unpack2(a0,x0,y0); unpack2(a1,x1,y1); unpack2(a2,x2,y2); unpack2(a3,x3,y3);
    float s = ((x0+y0)+(x1+y1)) + ((x2+y2)+(x3+y3));
    float p = __expf(s);
    l += p;
    u64 ps = pack2(p, p);
    const ulonglong2* vr = (const ulonglong2*)(Vsh + j*68);
    #pragma unroll
    for (int cc = 0; cc < 16; cc++){
      ulonglong2 vv = vr[cc];
      ffma2(acc[2*cc],   ps, vv.x);
      ffma2(acc[2*cc+1], ps, vv.y);
    }
  }
  __syncthreads();
  if (grp == 1){
    float* dst = Ksh + pix*68;
    #pragma unroll
    for (int cc = 0; cc < 32; cc++) *(u64*)(dst + 2*cc) = acc[cc];
    dst[64] = l;
  }
  __syncthreads();
  if (grp == 0){
    const float* src = Ksh + pix*68;
    l += src[64];
    float gam = gamma_p[0] / l;
    const float* Xb = (x_slice >= 0) ? g_scratch + (size_t)x_slice*NELEM + base : nullptr;
    #pragma unroll
    for (int cc = 0; cc < 32; cc++){
      float a0, a1; unpack2(acc[cc], a0, a1);
      float2 o2 = *(const float2*)(src + 2*cc);
      a0 = gam*(a0 + o2.x);
      a1 = gam*(a1 + o2.y);
      if (Xb){
        a0 += Xb[(size_t)(2*cc)*NN + pix];
        a1 += Xb[(size_t)(2*cc+1)*NN + pix];
      }
      Ob[(size_t)(2*cc)*NN + pix]   = a0;
      Ob[(size_t)(2*cc+1)*NN + pix] = a1;
    }
  }
}

// ================= per-plane 192x192 transpose (optional fused add) =================
__global__ void k_transpose(int in_slice, int out_slice, int add_slice)
{
  __shared__ float tile[32][33];
  const float* in = g_scratch + (size_t)in_slice*NELEM + (size_t)blockIdx.z*NN;
  float* out      = g_scratch + (size_t)out_slice*NELEM + (size_t)blockIdx.z*NN;
  const float* ad = (add_slice >= 0) ? g_scratch + (size_t)add_slice*NELEM + (size_t)blockIdx.z*NN : nullptr;
  int x0 = blockIdx.x*32, y0 = blockIdx.y*32;
  int tx = threadIdx.x, ty = threadIdx.y;
  #pragma unroll
  for (int k = 0; k < 32; k += 8)
    tile[ty+k][tx] = in[(size_t)(y0+ty+k)*WW + x0+tx];
  __syncthreads();
  #pragma unroll
  for (int k = 0; k < 32; k += 8){
    float v = tile[tx][ty+k];
    size_t oidx = (size_t)(x0+ty+k)*HH + y0+tx;
    if (ad) v += ad[oidx];
    out[oidx] = v;
  }
}

extern "C" void kernel_launch(void* const* d_in, const int* in_sizes, int n_in,
                              void* d_out, int out_size)
{
  const float* x    = (const float*)d_in[0];
  const float* pw_w = (const float*)d_in[1];
  const float* dw_w = (const float*)d_in[2];
  const float* dw_b = (const float*)d_in[3];
  const float* c2w  = (const float*)d_in[4];
  const float* c2b  = (const float*)d_in[5];
  const float* c0w  = (const float*)d_in[6];
  const float* c0b  = (const float*)d_in[7];
  const float* aq   = (const float*)d_in[8];
  const float* ak   = (const float*)d_in[9];
  const float* av   = (const float*)d_in[10];
  const float* ap   = (const float*)d_in[11];
  const float* temp = (const float*)d_in[12];
  const float* rq   = (const float*)d_in[13];
  const float* rk   = (const float*)d_in[14];
  const float* rv   = (const float*)d_in[15];
  const float* rg   = (const float*)d_in[16];
  const float* cq   = (const float*)d_in[17];
  const float* ck   = (const float*)d_in[18];
  const float* cv   = (const float*)d_in[19];
  const float* cg   = (const float*)d_in[20];
  const float* fw   = (const float*)d_in[21];
  const float* fb   = (const float*)d_in[22];
  float* out = (float*)d_out;

  const int T256 = (BATCH*NN)/256;                 // 576
  const int T128 = (BATCH*NN)/TP;                  // 1152
  const int SM_W1 = (64*256 + 64*68)*4;            // 82944
  const int SM_W2 = (64*TP  + 2*64*68)*4;          // 67584
  const int SM_DI = (64*256 + 2*64*68)*4;          // 100352
  const int SM_AP = (64*256 + 64*36)*4;            // 74752
  const int SM_LA = 2*192*68*4;                    // 104448
  cudaFuncSetAttribute(k_convW1, cudaFuncAttributeMaxDynamicSharedMemorySize, SM_W1);
  cudaFuncSetAttribute(k_convW2, cudaFuncAttributeMaxDynamicSharedMemorySize, SM_W2);
  cudaFuncSetAttribute(k_convDI, cudaFuncAttributeMaxDynamicSharedMemorySize, SM_DI);
  cudaFuncSetAttribute(k_final3, cudaFuncAttributeMaxDynamicSharedMemorySize, SM_W1);
  cudaFuncSetAttribute(k_apply_t,cudaFuncAttributeMaxDynamicSharedMemorySize, SM_AP);
  cudaFuncSetAttribute(k_lineattn,cudaFuncAttributeMaxDynamicSharedMemorySize, SM_LA);

  // t = pw(x); gelu(dw(t)+b); x1 = conv2(u)+b2 + conv0(x)+b0
  k_convW1<<<T256,256,SM_W1>>>(x, -1, nullptr, 0, pw_w, 64, nullptr, 0);
  k_dwgelu<<<NELEM/256,256>>>(0, 1, dw_w, dw_b);
  k_convDI<<<T256,256,SM_DI>>>(1, x, 2, c2w, c2b, c0w, c0b);

  // channel attention -> out1 (slice 7)
  k_convW2<<<T128,256,SM_W2>>>(2, 3, 4, aq, ak);
  k_convW1<<<T256,256,SM_W1>>>(nullptr, 2, nullptr, 5, av, 64, nullptr, 0);
  k_gram<<<512,256>>>(3, 4);
  k_attnsoft<<<8,1024>>>(temp);
  k_apply_t<<<T256,256,SM_AP>>>(5, 6);
  k_convW1<<<T256,256,SM_W1>>>(nullptr, 6, nullptr, 7, ap, 64, nullptr, 0);

  // row attention -> out2 (slice 8); rv+cv fused (both read out1)
  k_convW2<<<T128,256,SM_W2>>>(2, 3, 4, rq, rk);
  k_convW2<<<T128,256,SM_W2>>>(7, 5, 9, rv, cv);
  k_lineattn<<<768,384,SM_LA>>>(3, 4, 5, 2, 8, rg);

  // col attention -> out3 (slice 9)
  k_convW2<<<T128,256,SM_W2>>>(2, 3, 4, cq, ck);
  dim3 tg(6,6,BATCH*CC), tb(32,8);
  k_transpose<<<tg,tb>>>(3, 0, -1);
  k_transpose<<<tg,tb>>>(4, 1, -1);
  k_transpose<<<tg,tb>>>(9, 6, -1);
  k_lineattn<<<768,384,SM_LA>>>(0, 1, 6, -1, 3, cg);
  k_transpose<<<tg,tb>>>(3, 9, 2);

  // fuse
  k_final3<<<T256,256,SM_W1>>>(7, 8, 9, fw, fb, out);
}

// round 15
// speedup vs baseline: 1.0820x; 1.0034x over previous
#include <cuda_runtime.h>
#include <math.h>
#include <stdint.h>

#define BATCH 4
#define CC 64
#define HH 192
#define WW 192
#define NN (HH*WW)
#define NELEM (BATCH*CC*NN)

__device__ float g_scratch[(size_t)11 * NELEM];
__device__ float g_gram[512*1024];
__device__ float g_normp[512*64];
__device__ float g_attnw[8*1024];

typedef unsigned long long u64;

__device__ __forceinline__ u64 pack2(float a, float b){
  u64 r;
  asm("mov.b64 %0, {%1,%2};" : "=l"(r) : "r"(__float_as_uint(a)), "r"(__float_as_uint(b)));
  return r;
}
__device__ __forceinline__ void unpack2(u64 v, float &a, float &b){
  unsigned lo, hi;
  asm("mov.b64 {%0,%1}, %2;" : "=r"(lo), "=r"(hi) : "l"(v));
  a = __uint_as_float(lo); b = __uint_as_float(hi);
}
__device__ __forceinline__ void ffma2(u64 &d, u64 a, u64 b){
  asm("fma.rn.f32x2 %0, %1, %2, %0;" : "+l"(d) : "l"(a), "l"(b));
}
__device__ __forceinline__ float gelu_f(float x){
  return 0.5f*x*(1.0f + erff(x*0.70710678118654752f));
}

// ---- tf32 split: x ~= h + l, both tf32 (rna) ----
__device__ __forceinline__ void tf32_split(float x, uint32_t &h, uint32_t &l){
  asm("cvt.rna.tf32.f32 %0, %1;" : "=r"(h) : "f"(x));
  float r = x - __uint_as_float(h);
  asm("cvt.rna.tf32.f32 %0, %1;" : "=r"(l) : "f"(r));
}

// ---- m16n8k8 tf32 mma, D=C in-place ----
__device__ __forceinline__ void mma_tf32(float* d, const uint32_t* a, const uint32_t* b){
  asm volatile(
    "mma.sync.aligned.m16n8k8.row.col.f32.tf32.tf32.f32 "
    "{%0,%1,%2,%3},{%4,%5,%6,%7},{%8,%9},{%0,%1,%2,%3};"
    : "+f"(d[0]), "+f"(d[1]), "+f"(d[2]), "+f"(d[3])
    : "r"(a[0]), "r"(a[1]), "r"(a[2]), "r"(a[3]), "r"(b[0]), "r"(b[1]));
}

#define WS_STRIDE 68
#define XS_STRIDE 136
#define MMA_SMEM ((128*WS_STRIDE + 64*XS_STRIDE)*4)   // 69632 B

// ================= tensor-core conv1x1 =================
// D[set][64, 128px] = w_set[64,64] @ X[64,128], tf32 3-term split, 1-3 K-phases.
// outA = set0 dest slice (or ext_out if -1). outB (>=0) enables dual-set with wB.
__global__ void __launch_bounds__(256,2) k_mma(
    const float* __restrict__ ext_in,
    int s0, int s1, int s2,
    float* __restrict__ ext_out, int outA, int outB,
    const float* __restrict__ w0, int ldw0, int coff0,
    const float* __restrict__ w1, int ldw1, int coff1,
    const float* __restrict__ w2, int ldw2, int coff2,
    const float* __restrict__ wB,
    const float* __restrict__ biasA, const float* __restrict__ biasA2, int do_gelu)
{
  extern __shared__ float sm[];
  float* ws = sm;                 // [128][68]  ws[m*68+k] = w[m][k] (rows 64-127: set1)
  float* xs = sm + 128*WS_STRIDE; // [64][136]  xs[k*136+px] = X[k][px]
  int tid = threadIdx.x, lane = tid & 31, wid = tid >> 5;
  int gid = lane >> 2, tig = lane & 3;
  int m0 = (wid & 3) * 16;
  int n0 = (wid >> 2) * 64;
  int nphase = (w1 == nullptr) ? 1 : ((w2 == nullptr) ? 2 : 3);
  bool dual = (wB != nullptr);

  int p0 = blockIdx.x * 128;
  int b = p0 / NN, n0blk = p0 - b*NN;
  size_t boff = (size_t)b*(CC*NN) + n0blk;

  float acc0[32], acc1[32];
  #pragma unroll
  for (int i = 0; i < 32; i++){ acc0[i] = 0.f; acc1[i] = 0.f; }

  for (int p = 0; p < nphase; p++){
    if (p) __syncthreads();    // all warps done with previous phase's smem
    const float* wp = (p==0) ? w0 : (p==1) ? w1 : w2;
    int ldw  = (p==0) ? ldw0  : (p==1) ? ldw1  : ldw2;
    int coff = (p==0) ? coff0 : (p==1) ? coff1 : coff2;
    int sl   = (p==0) ? s0 : (p==1) ? s1 : s2;
    const float* xin = (sl >= 0) ? g_scratch + (size_t)sl*NELEM : ext_in;
    const float* xb = xin + boff;

    for (int i = tid; i < 4096; i += 256){
      int m = i >> 6, k = i & 63;
      ws[m*WS_STRIDE + k] = wp[m*ldw + coff + k];
    }
    if (dual){
      for (int i = tid; i < 4096; i += 256){
        int m = i >> 6, k = i & 63;
        ws[(64+m)*WS_STRIDE + k] = wB[m*64 + k];
      }
    }
    for (int i = tid; i < 2048; i += 256){
      int c = i >> 5, q = i & 31;
      *(float4*)(xs + c*XS_STRIDE + q*4) = *(const float4*)(xb + (size_t)c*NN + q*4);
    }
    __syncthreads();

    #pragma unroll
    for (int ks = 0; ks < 8; ks++){
      // A fragments (set0): a[i] at rows {gid, gid+8}, cols {tig, tig+4} of [m0.., ks*8..]
      uint32_t ah0[4], al0[4], ah1[4], al1[4];
      {
        const float* wr = ws + (size_t)m0*WS_STRIDE + ks*8;
        tf32_split(wr[(gid  )*WS_STRIDE + tig    ], ah0[0], al0[0]);
        tf32_split(wr[(gid+8)*WS_STRIDE + tig    ], ah0[1], al0[1]);
        tf32_split(wr[(gid  )*WS_STRIDE + tig + 4], ah0[2], al0[2]);
        tf32_split(wr[(gid+8)*WS_STRIDE + tig + 4], ah0[3], al0[3]);
      }
      if (dual){
        const float* wr = ws + (size_t)(64+m0)*WS_STRIDE + ks*8;
        tf32_split(wr[(gid  )*WS_STRIDE + tig    ], ah1[0], al1[0]);
        tf32_split(wr[(gid+8)*WS_STRIDE + tig    ], ah1[1], al1[1]);
        tf32_split(wr[(gid  )*WS_STRIDE + tig + 4], ah1[2], al1[2]);
        tf32_split(wr[(gid+8)*WS_STRIDE + tig + 4], ah1[3], al1[3]);
      }
      #pragma unroll
      for (int nt = 0; nt < 8; nt++){
        // B fragment: rows(k) {tig, tig+4}, col(n) gid of [ks*8.., n0+nt*8..]
        uint32_t bh[2], bl[2];
        const float* xr = xs + (size_t)(ks*8)*XS_STRIDE + n0 + nt*8 + gid;
        tf32_split(xr[(size_t)tig*XS_STRIDE      ], bh[0], bl[0]);
        tf32_split(xr[(size_t)(tig+4)*XS_STRIDE  ], bh[1], bl[1]);
        float* d0 = acc0 + nt*4;
        mma_tf32(d0, ah0, bh);
        mma_tf32(d0, ah0, bl);
        mma_tf32(d0, al0, bh);
        if (dual){
          float* d1 = acc1 + nt*4;
          mma_tf32(d1, ah1, bh);
          mma_tf32(d1, ah1, bl);
          mma_tf32(d1, al1, bh);
        }
      }
    }
  }

  // ---- epilogue ----
  // c0:(row=gid, col=tig*2) c1:(gid, tig*2+1) c2:(gid+8, col) c3:(gid+8, col+1)
  {
    float* plane0 = (outA >= 0) ? g_scratch + (size_t)outA*NELEM : ext_out;
    int oA = m0 + gid, oB = m0 + gid + 8;
    float bA = 0.f, bB = 0.f;
    if (biasA){  bA += biasA[oA];  bB += biasA[oB]; }
    if (biasA2){ bA += biasA2[oA]; bB += biasA2[oB]; }
    float* rowA = plane0 + boff + (size_t)oA*NN + n0 + tig*2;
    float* rowB = plane0 + boff + (size_t)oB*NN + n0 + tig*2;
    #pragma unroll
    for (int nt = 0; nt < 8; nt++){
      float v0 = acc0[nt*4+0] + bA, v1 = acc0[nt*4+1] + bA;
      float v2 = acc0[nt*4+2] + bB, v3 = acc0[nt*4+3] + bB;
      if (do_gelu){ v0=gelu_f(v0); v1=gelu_f(v1); v2=gelu_f(v2); v3=gelu_f(v3); }
      *(float2*)(rowA + nt*8) = make_float2(v0, v1);
      *(float2*)(rowB + nt*8) = make_float2(v2, v3);
    }
    if (dual){
      float* plane1 = g_scratch + (size_t)outB*NELEM;
      float* rA = plane1 + boff + (size_t)oA*NN + n0 + tig*2;
      float* rB = plane1 + boff + (size_t)oB*NN + n0 + tig*2;
      #pragma unroll
      for (int nt = 0; nt < 8; nt++){
        *(float2*)(rA + nt*8) = make_float2(acc1[nt*4+0], acc1[nt*4+1]);
        *(float2*)(rB + nt*8) = make_float2(acc1[nt*4+2], acc1[nt*4+3]);
      }
    }
  }
}

// ================= channel-attention apply (block-diag 2x 32x32), FFMA2 =================
__global__ void __launch_bounds__(256,2) k_apply_t(int v_slice, int out_slice)
{
  extern __shared__ float sm[];
  float* xs = sm;             // [64][256]
  float* ws = sm + 64*256;    // [(g*32+k)*36 + o(<32)] = attn[b,g,o,k]
  int tid = threadIdx.x, lane = tid & 31, wid = tid >> 5;
  int og = (wid & 3) * 16;
  int ph = wid >> 2;
  int p0 = blockIdx.x * 256;
  int b = p0 / NN, n0 = p0 - b*NN;
  for (int i = tid; i < 2048; i += 256){
    int g = i >> 10, rem = i & 1023;
    int o = rem >> 5, k = rem & 31;
    ws[(g*32 + k)*36 + o] = g_attnw[(size_t)(b*2+g)*1024 + o*32 + k];
  }
  const float* xb = g_scratch + (size_t)v_slice*NELEM + (size_t)b*(CC*NN) + n0;
  for (int i = tid; i < 4096; i += 256){
    int c = i >> 6, q = i & 63;
    *(float4*)(xs + c*256 + q*4) = *(const float4*)(xb + (size_t)c*NN + q*4);
  }
  __syncthreads();
  int g = og >> 5;
  int ow = og & 31;
  u64 acc[32];
  u64 z = pack2(0.f, 0.f);
  #pragma unroll
  for (int i = 0; i < 32; i++) acc[i] = z;
  const float* xrow = xs + (size_t)g*32*256 + ph*128 + lane*4;
  const float* wrow = ws + (size_t)g*32*36 + ow;
  #pragma unroll 4
  for (int k = 0; k < 32; k++){
    float4 xv = *(const float4*)(xrow + k*256);
    u64 s0 = pack2(xv.x, xv.x), s1 = pack2(xv.y, xv.y);
    u64 s2 = pack2(xv.z, xv.z), s3 = pack2(xv.w, xv.w);
    const float* wk = wrow + k*36;
    ulonglong2 w0 = *(const ulonglong2*)(wk);
    ulonglong2 w1 = *(const ulonglong2*)(wk + 4);
    ulonglong2 w2 = *(const ulonglong2*)(wk + 8);
    ulonglong2 w3 = *(const ulonglong2*)(wk + 12);
    ffma2(acc[0],  w0.x, s0); ffma2(acc[1],  w0.x, s1);
    ffma2(acc[2],  w0.x, s2); ffma2(acc[3],  w0.x, s3);
    ffma2(acc[4],  w0.y, s0); ffma2(acc[5],  w0.y, s1);
    ffma2(acc[6],  w0.y, s2); ffma2(acc[7],  w0.y, s3);
    ffma2(acc[8],  w1.x, s0); ffma2(acc[9],  w1.x, s1);
    ffma2(acc[10], w1.x, s2); ffma2(acc[11], w1.x, s3);
    ffma2(acc[12], w1.y, s0); ffma2(acc[13], w1.y, s1);
    ffma2(acc[14], w1.y, s2); ffma2(acc[15], w1.y, s3);
    ffma2(acc[16], w2.x, s0); ffma2(acc[17], w2.x, s1);
    ffma2(acc[18], w2.x, s2); ffma2(acc[19], w2.x, s3);
    ffma2(acc[20], w2.y, s0); ffma2(acc[21], w2.y, s1);
    ffma2(acc[22], w2.y, s2); ffma2(acc[23], w2.y, s3);
    ffma2(acc[24], w3.x, s0); ffma2(acc[25], w3.x, s1);
    ffma2(acc[26], w3.x, s2); ffma2(acc[27], w3.x, s3);
    ffma2(acc[28], w3.y, s0); ffma2(acc[29], w3.y, s1);
    ffma2(acc[30], w3.y, s2); ffma2(acc[31], w3.y, s3);
  }
  float* yb = g_scratch + (size_t)out_slice*NELEM + (size_t)b*(CC*NN) + n0;
  #pragma unroll
  for (int p = 0; p < 8; p++){
    float lo0,hi0,lo1,hi1,lo2,hi2,lo3,hi3;
    unpack2(acc[p*4+0], lo0, hi0);
    unpack2(acc[p*4+1], lo1, hi1);
    unpack2(acc[p*4+2], lo2, hi2);
    unpack2(acc[p*4+3], lo3, hi3);
    int o = og + 2*p;
    int pbase = ph*128 + lane*4;
    *(float4*)(yb + (size_t)o*NN     + pbase) = make_float4(lo0,lo1,lo2,lo3);
    *(float4*)(yb + (size_t)(o+1)*NN + pbase) = make_float4(hi0,hi1,hi2,hi3);
  }
}

// ================= depthwise 3x3 + bias + exact GELU =================
__global__ void __launch_bounds__(256) k_dwgelu(
    int in_slice, int out_slice,
    const float* __restrict__ dw_w, const float* __restrict__ dw_b)
{
  int e = blockIdx.x*256 + threadIdx.x;
  const float* tin = g_scratch + (size_t)in_slice*NELEM;
  int n  = e % NN;
  int bc = e / NN;
  int c  = bc & 63;
  int h = n / WW, w = n - h*WW;
  const float* plane = tin + (size_t)bc*NN;
  float s = dw_b[c];
  #pragma unroll
  for (int ky = 0; ky < 3; ky++){
    int hh = h + ky - 1;
    if ((unsigned)hh >= (unsigned)HH) continue;
    #pragma unroll
    for (int kx = 0; kx < 3; kx++){
      int wx = w + kx - 1;
      if ((unsigned)wx >= (unsigned)WW) continue;
      s += dw_w[c*9 + ky*3 + kx] * plane[hh*WW + wx];
    }
  }
  g_scratch[(size_t)out_slice*NELEM + e] = gelu_f(s);
}

// ================= split-K gram + norms =================
__global__ void __launch_bounds__(256) k_gram(int q_slice, int k_slice)
{
  int blk = blockIdx.x;
  int s  = blk & 63;
  int bg = blk >> 6;
  int g = bg & 1, b = bg >> 1;
  int n0 = s * 576;
  const float* qb = g_scratch + (size_t)q_slice*NELEM + (size_t)(b*64 + g*32)*NN;
  const float* kb = g_scratch + (size_t)k_slice*NELEM + (size_t)(b*64 + g*32)*NN;
  __shared__ float qs[32][65];
  __shared__ float ks[32][65];
  int t = threadIdx.x;
  int i = t & 31, jb = t >> 5;
  float acc[4] = {0.f,0.f,0.f,0.f};
  float nacc = 0.f;
  for (int ch = 0; ch < 9; ch++){
    int nb = n0 + ch*64;
    __syncthreads();
    for (int idx = t; idx < 2048; idx += 256){
      int r = idx >> 6, nn = idx & 63;
      qs[r][nn] = qb[(size_t)r*NN + nb + nn];
      ks[r][nn] = kb[(size_t)r*NN + nb + nn];
    }
    __syncthreads();
    #pragma unroll 8
    for (int nn = 0; nn < 64; nn++){
      float qv = qs[i][nn];
      acc[0] += qv * ks[jb*4+0][nn];
      acc[1] += qv * ks[jb*4+1][nn];
      acc[2] += qv * ks[jb*4+2][nn];
      acc[3] += qv * ks[jb*4+3][nn];
    }
    if (t < 32){
      #pragma unroll 8
      for (int nn = 0; nn < 64; nn++){ float v = qs[t][nn]; nacc += v*v; }
    } else if (t < 64){
      int r = t - 32;
      #pragma unroll 8
      for (int nn = 0; nn < 64; nn++){ float v = ks[r][nn]; nacc += v*v; }
    }
  }
  float* Gp = g_gram + (size_t)blk*1024;
  #pragma unroll
  for (int jj = 0; jj < 4; jj++) Gp[i*32 + jb*4 + jj] = acc[jj];
  if (t < 64) g_normp[(size_t)blk*64 + t] = nacc;
}

// ================= gram finalize + softmax =================
__global__ void __launch_bounds__(1024) k_attnsoft(const float* __restrict__ temperature)
{
  int bg = blockIdx.x;
  int g = bg & 1;
  int t = threadIdx.x;
  int i = t >> 5, j = t & 31;
  __shared__ float nq[32], nk[32];
  if (t < 64){
    float s = 0.f;
    for (int ss = 0; ss < 64; ss++) s += g_normp[(size_t)(bg*64 + ss)*64 + t];
    float nv = fmaxf(sqrtf(s), 1e-12f);
    if (t < 32) nq[t] = nv; else nk[t-32] = nv;
  }
  float G = 0.f;
  for (int ss = 0; ss < 64; ss++) G += g_gram[(size_t)(bg*64 + ss)*1024 + t];
  __syncthreads();
  float logit = G / (nq[i]*nk[j]) * temperature[g];
  float m = logit;
  #pragma unroll
  for (int o = 16; o > 0; o >>= 1) m = fmaxf(m, __shfl_xor_sync(0xffffffffu, m, o));
  float e = __expf(logit - m);
  float ssum = e;
  #pragma unroll
  for (int o = 16; o > 0; o >>= 1) ssum += __shfl_xor_sync(0xffffffffu, ssum, o);
  g_attnw[(size_t)bg*1024 + t] = e / ssum;
}

// ================= line attention, split-j across two 192-thread groups =================
__global__ void __launch_bounds__(384, 1) k_lineattn(
    int q_slice, int k_slice, int v_slice, int x_slice, int out_slice,
    const float* __restrict__ gamma_p)
{
  extern __shared__ float smem[];
  float* Ksh = smem;                 // [192][68], j-major
  float* Vsh = smem + 192*68;
  int blk = blockIdx.x;
  int h = blk % HH;
  int b = blk / HH;
  size_t base = (size_t)b*(CC*NN) + (size_t)h*WW;
  const float* Qb = g_scratch + (size_t)q_slice*NELEM + base;
  const float* Kb = g_scratch + (size_t)k_slice*NELEM + base;
  const float* Vb = g_scratch + (size_t)v_slice*NELEM + base;
  float* Ob = g_scratch + (size_t)out_slice*NELEM + base;
  int t = threadIdx.x;
  int pix = t % 192;
  int grp = t / 192;
  for (int idx = t; idx < 64*192; idx += 384){
    int c = idx / 192;
    int j = idx - c*192;
    Ksh[j*68 + c] = Kb[(size_t)c*NN + j];
    Vsh[j*68 + c] = Vb[(size_t)c*NN + j];
  }
  u64 q2[32];
  #pragma unroll
  for (int cc = 0; cc < 32; cc++)
    q2[cc] = pack2(Qb[(size_t)(2*cc)*NN + pix], Qb[(size_t)(2*cc+1)*NN + pix]);
  __syncthreads();
  u64 z = pack2(0.f, 0.f);
  u64 acc[32];
  #pragma unroll
  for (int cc = 0; cc < 32; cc++) acc[cc] = z;
  float l = 0.f;
  int j0 = grp * 96;
  #pragma unroll 2
  for (int j = j0; j < j0 + 96; j++){
    const ulonglong2* kr = (const ulonglong2*)(Ksh + j*68);
    u64 a0 = z, a1 = z, a2 = z, a3 = z;
    #pragma unroll
    for (int cc = 0; cc < 16; cc += 2){
      ulonglong2 kv0 = kr[cc];
      ulonglong2 kv1 = kr[cc+1];
      ffma2(a0, q2[2*cc+0], kv0.x);
      ffma2(a1, q2[2*cc+1], kv0.y);
      ffma2(a2, q2[2*cc+2], kv1.x);
      ffma2(a3, q2[2*cc+3], kv1.y);
    }
    float x0,y0,x1,y1,x2,y2,x3,y3;
    unpack2(a0,x0,y0); unpack2(a1,x1,y1); unpack2(a2,x2,y2); unpack2(a3,x3,y3);
    float s = ((x0+y0)+(x1+y1)) + ((x2+y2)+(x3+y3));
    float p = __expf(s);
    l += p;
    u64 ps = pack2(p, p);
    const ulonglong2* vr = (const ulonglong2*)(Vsh + j*68);
    #pragma unroll
    for (int cc = 0; cc < 16; cc++){
      ulonglong2 vv = vr[cc];
      ffma2(acc[2*cc],   ps, vv.x);
      ffma2(acc[2*cc+1], ps, vv.y);
    }
  }
  __syncthreads();
  if (grp == 1){
    float* dst = Ksh + pix*68;
    #pragma unroll
    for (int cc = 0; cc < 32; cc++) *(u64*)(dst + 2*cc) = acc[cc];
    dst[64] = l;
  }
  __syncthreads();
  if (grp == 0){
    const float* src = Ksh + pix*68;
    l += src[64];
    float gam = gamma_p[0] / l;
    const float* Xb = (x_slice >= 0) ? g_scratch + (size_t)x_slice*NELEM + base : nullptr;
    #pragma unroll
    for (int cc = 0; cc < 32; cc++){
      float a0, a1; unpack2(acc[cc], a0, a1);
      float2 o2 = *(const float2*)(src + 2*cc);
      a0 = gam*(a0 + o2.x);
      a1 = gam*(a1 + o2.y);
      if (Xb){
        a0 += Xb[(size_t)(2*cc)*NN + pix];
        a1 += Xb[(size_t)(2*cc+1)*NN + pix];
      }
      Ob[(size_t)(2*cc)*NN + pix]   = a0;
      Ob[(size_t)(2*cc+1)*NN + pix] = a1;
    }
  }
}

// ================= per-plane 192x192 transpose (optional fused add) =================
__global__ void k_transpose(int in_slice, int out_slice, int add_slice)
{
  __shared__ float tile[32][33];
  const float* in = g_scratch + (size_t)in_slice*NELEM + (size_t)blockIdx.z*NN;
  float* out      = g_scratch + (size_t)out_slice*NELEM + (size_t)blockIdx.z*NN;
  const float* ad = (add_slice >= 0) ? g_scratch + (size_t)add_slice*NELEM + (size_t)blockIdx.z*NN : nullptr;
  int x0 = blockIdx.x*32, y0 = blockIdx.y*32;
  int tx = threadIdx.x, ty = threadIdx.y;
  #pragma unroll
  for (int k = 0; k < 32; k += 8)
    tile[ty+k][tx] = in[(size_t)(y0+ty+k)*WW + x0+tx];
  __syncthreads();
  #pragma unroll
  for (int k = 0; k < 32; k += 8){
    float v = tile[tx][ty+k];
    size_t oidx = (size_t)(x0+ty+k)*HH + y0+tx;
    if (ad) v += ad[oidx];
    out[oidx] = v;
  }
}

extern "C" void kernel_launch(void* const* d_in, const int* in_sizes, int n_in,
                              void* d_out, int out_size)
{
  const float* x    = (const float*)d_in[0];
  const float* pw_w = (const float*)d_in[1];
  const float* dw_w = (const float*)d_in[2];
  const float* dw_b = (const float*)d_in[3];
  const float* c2w  = (const float*)d_in[4];
  const float* c2b  = (const float*)d_in[5];
  const float* c0w  = (const float*)d_in[6];
  const float* c0b  = (const float*)d_in[7];
  const float* aq   = (const float*)d_in[8];
  const float* ak   = (const float*)d_in[9];
  const float* av   = (const float*)d_in[10];
  const float* ap   = (const float*)d_in[11];
  const float* temp = (const float*)d_in[12];
  const float* rq   = (const float*)d_in[13];
  const float* rk   = (const float*)d_in[14];
  const float* rv   = (const float*)d_in[15];
  const float* rg   = (const float*)d_in[16];
  const float* cq   = (const float*)d_in[17];
  const float* ck   = (const float*)d_in[18];
  const float* cv   = (const float*)d_in[19];
  const float* cg   = (const float*)d_in[20];
  const float* fw   = (const float*)d_in[21];
  const float* fb   = (const float*)d_in[22];
  float* out = (float*)d_out;

  const int TG = (BATCH*NN)/128;                   // 1152
  const int T256 = (BATCH*NN)/256;                 // 576
  const int SM_AP = (64*256 + 64*36)*4;
  const int SM_LA = 2*192*68*4;
  cudaFuncSetAttribute(k_mma,     cudaFuncAttributeMaxDynamicSharedMemorySize, MMA_SMEM);
  cudaFuncSetAttribute(k_apply_t, cudaFuncAttributeMaxDynamicSharedMemorySize, SM_AP);
  cudaFuncSetAttribute(k_lineattn,cudaFuncAttributeMaxDynamicSharedMemorySize, SM_LA);

  // t = pw(x)
  k_mma<<<TG,256,MMA_SMEM>>>(x, -1, 0, 0, nullptr, 0, -1,
      pw_w, 64, 0, nullptr, 0, 0, nullptr, 0, 0, nullptr, nullptr, nullptr, 0);
  // gelu(dw(t)+b)
  k_dwgelu<<<NELEM/256,256>>>(0, 1, dw_w, dw_b);
  // x1 = conv2(u)+b2 + conv0(x)+b0 : 2-phase
  k_mma<<<TG,256,MMA_SMEM>>>(x, 1, -1, 0, nullptr, 2, -1,
      c2w, 64, 0, c0w, 64, 0, nullptr, 0, 0, nullptr, c2b, c0b, 0);

  // channel attention -> out1 (slice 7)
  k_mma<<<TG,256,MMA_SMEM>>>(nullptr, 2, 0, 0, nullptr, 3, 4,
      aq, 64, 0, nullptr, 0, 0, nullptr, 0, 0, ak, nullptr, nullptr, 0);
  k_mma<<<TG,256,MMA_SMEM>>>(nullptr, 2, 0, 0, nullptr, 5, -1,
      av, 64, 0, nullptr, 0, 0, nullptr, 0, 0, nullptr, nullptr, nullptr, 0);
  k_gram<<<512,256>>>(3, 4);
  k_attnsoft<<<8,1024>>>(temp);
  k_apply_t<<<T256,256,SM_AP>>>(5, 6);
  k_mma<<<TG,256,MMA_SMEM>>>(nullptr, 6, 0, 0, nullptr, 7, -1,
      ap, 64, 0, nullptr, 0, 0, nullptr, 0, 0, nullptr, nullptr, nullptr, 0);

  // row attention -> out2 (slice 8)
  k_mma<<<TG,256,MMA_SMEM>>>(nullptr, 2, 0, 0, nullptr, 3, 4,
      rq, 64, 0, nullptr, 0, 0, nullptr, 0, 0, rk, nullptr, nullptr, 0);
  k_mma<<<TG,256,MMA_SMEM>>>(nullptr, 7, 0, 0, nullptr, 5, 9,
      rv, 64, 0, nullptr, 0, 0, nullptr, 0, 0, cv, nullptr, nullptr, 0);
  k_lineattn<<<768,384,SM_LA>>>(3, 4, 5, 2, 8, rg);

  // col attention -> out3 (slice 9)
  k_mma<<<TG,256,MMA_SMEM>>>(nullptr, 2, 0, 0, nullptr, 3, 4,
      cq, 64, 0, nullptr, 0, 0, nullptr, 0, 0, ck, nullptr, nullptr, 0);
  dim3 tg(6,6,BATCH*CC), tb(32,8);
  k_transpose<<<tg,tb>>>(3, 0, -1);
  k_transpose<<<tg,tb>>>(4, 1, -1);
  k_transpose<<<tg,tb>>>(9, 6, -1);
  k_lineattn<<<768,384,SM_LA>>>(0, 1, 6, -1, 3, cg);
  k_transpose<<<tg,tb>>>(3, 9, 2);

  // fuse: 3-phase 192->64 + bias + gelu -> d_out
  k_mma<<<TG,256,MMA_SMEM>>>(nullptr, 7, 8, 9, out, -1, -1,
      fw, 192, 0, fw, 192, 64, fw, 192, 128, nullptr, fb, nullptr, 1);
}